// round 14
// baseline (speedup 1.0000x reference)
#include <cuda_runtime.h>
#include <cuda_fp16.h>
#include <math.h>
#include <stdint.h>

// ---------------- Problem constants ----------------
#define DIMV    512
#define HEADS   16
#define DHEAD   32
#define NWIN    512
#define NTOK    65
#define NROWS   (NWIN*NTOK)  // 33280
#define NB      8
#define DEPTH   4
#define QSCALE  0.17677669529663687f
#define LOCAL_ELEMS (8*64*64*512)

// ---------------- helpers ----------------
__device__ __forceinline__ uint32_t smem_to_u32(const void* p) {
    uint32_t a;
    asm("{ .reg .u64 t; cvta.to.shared.u64 t, %1; cvt.u32.u64 %0, t; }" : "=r"(a) : "l"(p));
    return a;
}
__device__ __forceinline__ void cp16(uint32_t dst, const void* src) {
    asm volatile("cp.async.cg.shared.global [%0], [%1], 16;\n" :: "r"(dst), "l"(src));
}
__device__ __forceinline__ void cp_commit() { asm volatile("cp.async.commit_group;\n" ::: "memory"); }
__device__ __forceinline__ float gelu_exact(float x) {
    return 0.5f * x * (1.0f + erff(x * 0.70710678118654752f));
}
__device__ __forceinline__ uint32_t h2_u32(__half2 v) {
    return *(uint32_t*)&v;
}

// ================= Scratch =================
__device__ __align__(16) float  g_xw  [NROWS*DIMV];
__device__ __align__(16) __half g_h   [NROWS*DIMV];
__device__ __align__(16) __half g_qkv [NROWS*3*DIMV];
__device__ __align__(16) __half g_o   [NROWS*DIMV];
__device__ __align__(16) __half g_m1  [NROWS*4*DIMV];
__device__ __align__(16) float  g_bias[HEADS*NTOK*NTOK];
__device__ __align__(16) __half g_hr  [NWIN*DIMV];
__device__ __align__(16) __half g_qkvr[NWIN*3*DIMV];
__device__ __align__(16) __half g_or  [NWIN*DIMV];
__device__ __align__(16) __half g_Wqkv[DEPTH*3*DIMV*DIMV];
__device__ __align__(16) __half g_Wout[DEPTH*DIMV*DIMV];
__device__ __align__(16) __half g_W1h [DEPTH*4*DIMV*DIMV];
__device__ __align__(16) __half g_W2h [DEPTH*DIMV*4*DIMV];

// ================= pack / unpack =================
__global__ void pack_kernel(const float* __restrict__ local_t, const float* __restrict__ region_t) {
    int idx = blockIdx.x * blockDim.x + threadIdx.x;
    if (idx >= NROWS*DIMV) return;
    int d = idx & 511, row = idx >> 9;
    int win = row / NTOK, t = row - win*NTOK;
    float v;
    if (t == 0) v = region_t[win*DIMV + d];
    else {
        int a = t - 1, p1 = a >> 3, p2 = a & 7;
        int b = win >> 6, rh = (win >> 3) & 7, rw = win & 7;
        v = local_t[(((b*64) + (rh*8 + p1))*64 + (rw*8 + p2))*DIMV + d];
    }
    g_xw[idx] = v;
}

__global__ void unpack_kernel(float* __restrict__ out) {
    int idx = blockIdx.x * blockDim.x + threadIdx.x;
    if (idx >= NROWS*DIMV) return;
    if (idx < LOCAL_ELEMS) {
        int d = idx & 511, p = idx >> 9;
        int col = p & 63, rowi = (p >> 6) & 63, b = p >> 12;
        int rh = rowi >> 3, p1 = rowi & 7, rw = col >> 3, p2 = col & 7;
        int win = b*64 + rh*8 + rw, t = 1 + p1*8 + p2;
        out[idx] = g_xw[(win*NTOK + t)*DIMV + d];
    } else {
        int r = idx - LOCAL_ELEMS, w = r >> 9, d = r & 511;
        out[idx] = g_xw[(w*NTOK)*DIMV + d];
    }
}

// ---- coalesced weight conversion: 32x32 tiled transpose + bias table ----
#define SEG_QKV (3*DIMV*DIMV)
#define SEG_OUT (DIMV*DIMV)
#define SEG_W1  (DIMV*4*DIMV)
#define SEG_W2  (4*DIMV*DIMV)
#define BIAS_N  (HEADS*NTOK*NTOK)
// tiles: qkv 16x48*4=3072, out 16x16*4=1024, w1 16x64*4=4096, w2 64x16*4=4096
#define T_QKV 3072
#define T_OUT (T_QKV + 1024)
#define T_W1  (T_OUT + 4096)
#define T_W2  (T_W1 + 4096)   // 12288
#define BIAS_BLKS ((BIAS_N + 255)/256)

__global__ __launch_bounds__(256) void wconv_all(
    const float* __restrict__ wqkv, const float* __restrict__ wout,
    const float* __restrict__ w1, const float* __restrict__ w2,
    const float* __restrict__ emb)
{
    int bid = blockIdx.x;
    if (bid < T_W2) {
        const float* W; __half* O; int K, N, r;
        if (bid < T_QKV) {
            int l = bid / 768; r = bid - l*768;
            W = wqkv + (size_t)l*SEG_QKV; O = g_Wqkv + (size_t)l*SEG_QKV; K = DIMV; N = 3*DIMV;
        } else if (bid < T_OUT) {
            int q = bid - T_QKV; int l = q / 256; r = q - l*256;
            W = wout + (size_t)l*SEG_OUT; O = g_Wout + (size_t)l*SEG_OUT; K = DIMV; N = DIMV;
        } else if (bid < T_W1) {
            int q = bid - T_OUT; int l = q / 1024; r = q - l*1024;
            W = w1 + (size_t)l*SEG_W1; O = g_W1h + (size_t)l*SEG_W1; K = DIMV; N = 4*DIMV;
        } else {
            int q = bid - T_W1; int l = q / 1024; r = q - l*1024;
            W = w2 + (size_t)l*SEG_W2; O = g_W2h + (size_t)l*SEG_W2; K = 4*DIMV; N = DIMV;
        }
        int tilesN = N >> 5;
        int tk = r / tilesN, tn = r - tk*tilesN;
        int k0 = tk*32, n0 = tn*32;
        __shared__ float tile[32][33];
        int tx = threadIdx.x & 31, ty = threadIdx.x >> 5;
        #pragma unroll
        for (int i = 0; i < 4; i++)                  // read coalesced along n
            tile[ty + i*8][tx] = W[(size_t)(k0 + ty + i*8)*N + n0 + tx];
        __syncthreads();
        #pragma unroll
        for (int i = 0; i < 4; i++)                  // write coalesced along k
            O[(size_t)(n0 + ty + i*8)*K + k0 + tx] = __float2half_rn(tile[tx][ty + i*8]);
    } else {
        int r = (bid - T_W2)*256 + threadIdx.x;
        if (r >= BIAS_N) return;
        int h = r / (NTOK*NTOK);
        int q = r - h*NTOK*NTOK;
        int i = q / NTOK, j = q - i*NTOK;
        float v = 0.f;
        if (i > 0 && j > 0) {
            int a = i - 1, b = j - 1;
            int r0 = (a >> 3) - (b >> 3) + 7;
            int r1 = (a & 7) - (b & 7) + 7;
            v = emb[(r0 + r1*15)*HEADS + h];
        }
        g_bias[r] = v;
    }
}

// ================= LayerNorm -> fp16, warp-per-row =================
__global__ __launch_bounds__(256) void ln_half(const float* __restrict__ x, int instr,
                                               const float* __restrict__ g,
                                               const float* __restrict__ b,
                                               __half* __restrict__ y) {
    int w = threadIdx.x >> 5, lane = threadIdx.x & 31;
    int row = blockIdx.x*8 + w;
    const float4* xv = (const float4*)(x + (size_t)row*instr);
    float4 v[4];
    float s = 0.f, s2 = 0.f;
    #pragma unroll
    for (int i = 0; i < 4; i++) {
        v[i] = xv[lane + 32*i];
        s  += v[i].x + v[i].y + v[i].z + v[i].w;
        s2 += v[i].x*v[i].x + v[i].y*v[i].y + v[i].z*v[i].z + v[i].w*v[i].w;
    }
    #pragma unroll
    for (int off = 16; off; off >>= 1) {
        s  += __shfl_xor_sync(0xffffffffu, s,  off);
        s2 += __shfl_xor_sync(0xffffffffu, s2, off);
    }
    float mean = s * (1.f/512.f);
    float var  = s2 * (1.f/512.f) - mean*mean;
    float rstd = rsqrtf(var + 1e-3f);
    __half2* p = (__half2*)(y + (size_t)row*DIMV);
    #pragma unroll
    for (int i = 0; i < 4; i++) {
        float4 gg = ((const float4*)g)[lane + 32*i];
        float4 bb = ((const float4*)b)[lane + 32*i];
        __half2 o01 = __floats2half2_rn((v[i].x - mean)*rstd*gg.x + bb.x, (v[i].y - mean)*rstd*gg.y + bb.y);
        __half2 o23 = __floats2half2_rn((v[i].z - mean)*rstd*gg.z + bb.z, (v[i].w - mean)*rstd*gg.w + bb.w);
        p[(lane + 32*i)*2]     = o01;
        p[(lane + 32*i)*2 + 1] = o23;
    }
}

// ================= Tensor-core attention (R11 proven) =================
template<int NT>
__global__ __launch_bounds__(256) void attn_tc(const __half* __restrict__ qkv,
                                               const float* __restrict__ biasTab,
                                               __half* __restrict__ o) {
    constexpr int TOK_PAD = (NT + 15) & ~15;
    constexpr int ST = TOK_PAD / 8;
    constexpr int QB = TOK_PAD / 16;
    constexpr int KS = TOK_PAD / 16;
    constexpr int QROWB = 80, KROWB = 80, VROWB = TOK_PAD*2 + 16;
    constexpr int PW = TOK_PAD*QROWB + TOK_PAD*KROWB + 32*VROWB;
    extern __shared__ __align__(16) char smattn[];
    const int w = threadIdx.x >> 5, lane = threadIdx.x & 31;
    char* spq = smattn + w * PW;
    char* spk = spq + TOK_PAD*QROWB;
    char* spv = spk + TOK_PAD*KROWB;
    const uint32_t uq = smem_to_u32(spq);
    const uint32_t uk = smem_to_u32(spk);
    const uint32_t uv = smem_to_u32(spv);
    const int tokbase = blockIdx.x * NT;
    const int g = lane >> 2, tig = lane & 3;

    for (int hh = 0; hh < 2; hh++) {
        const int h = w*2 + hh;
        for (int p = lane; p < NT*16; p += 32) {
            int tok = p >> 4, d2 = p & 15;
            const __half2* src = (const __half2*)(qkv + (size_t)(tokbase + tok)*(3*DIMV) + h*DHEAD + d2*2);
            __half2 qv = src[0];
            float2 qf = __half22float2(qv);
            *(__half2*)(spq + tok*QROWB + d2*4) = __floats2half2_rn(qf.x*QSCALE, qf.y*QSCALE);
            *(__half2*)(spk + tok*KROWB + d2*4) = src[DIMV/2];
            __half2 vv = src[DIMV];
            *(__half*)(spv + (2*d2)*VROWB   + tok*2) = __low2half(vv);
            *(__half*)(spv + (2*d2+1)*VROWB + tok*2) = __high2half(vv);
        }
        if (TOK_PAD > NT) {
            for (int p = lane; p < 32*(TOK_PAD - NT); p += 32) {
                int d = p / (TOK_PAD - NT), c = p - d*(TOK_PAD - NT);
                *(__half*)(spv + d*VROWB + (NT + c)*2) = __ushort_as_half(0);
            }
        }
        __syncwarp();

        for (int qb = 0; qb < QB; qb++) {
            uint32_t afr[2][4];
            #pragma unroll
            for (int kk = 0; kk < 2; kk++) {
                uint32_t addr = uq + (qb*16 + (lane & 15))*QROWB + (lane >> 4)*16 + kk*32;
                asm volatile("ldmatrix.sync.aligned.m8n8.x4.shared.b16 {%0,%1,%2,%3}, [%4];"
                    : "=r"(afr[kk][0]), "=r"(afr[kk][1]), "=r"(afr[kk][2]), "=r"(afr[kk][3]) : "r"(addr));
            }
            float s[ST][4];
            #pragma unroll
            for (int t = 0; t < ST; t++) { s[t][0]=0.f; s[t][1]=0.f; s[t][2]=0.f; s[t][3]=0.f; }
            #pragma unroll
            for (int t = 0; t < ST; t++) {
                #pragma unroll
                for (int kk = 0; kk < 2; kk++) {
                    uint32_t b[2];
                    uint32_t addr = uk + (t*8 + (lane & 7))*KROWB + ((lane >> 3) & 1)*16 + kk*32;
                    asm volatile("ldmatrix.sync.aligned.m8n8.x2.shared.b16 {%0,%1}, [%2];"
                        : "=r"(b[0]), "=r"(b[1]) : "r"(addr));
                    asm volatile(
                        "mma.sync.aligned.m16n8k16.row.col.f32.f16.f16.f32 "
                        "{%0,%1,%2,%3}, {%4,%5,%6,%7}, {%8,%9}, {%0,%1,%2,%3};"
                        : "+f"(s[t][0]), "+f"(s[t][1]), "+f"(s[t][2]), "+f"(s[t][3])
                        : "r"(afr[kk][0]), "r"(afr[kk][1]), "r"(afr[kk][2]), "r"(afr[kk][3]),
                          "r"(b[0]), "r"(b[1]));
                }
            }
            const int row0 = qb*16 + g;
            #pragma unroll
            for (int t = 0; t < ST; t++) {
                int c0 = t*8 + tig*2;
                if (biasTab) {
                    if (row0 < NT) {
                        if (c0 < NT)     s[t][0] += biasTab[(h*NT + row0)*NT + c0];
                        if (c0 + 1 < NT) s[t][1] += biasTab[(h*NT + row0)*NT + c0 + 1];
                    }
                    if (row0 + 8 < NT) {
                        if (c0 < NT)     s[t][2] += biasTab[(h*NT + row0 + 8)*NT + c0];
                        if (c0 + 1 < NT) s[t][3] += biasTab[(h*NT + row0 + 8)*NT + c0 + 1];
                    }
                }
                if (c0 >= NT)     { s[t][0] = -1e30f; s[t][2] = -1e30f; }
                if (c0 + 1 >= NT) { s[t][1] = -1e30f; s[t][3] = -1e30f; }
            }
            float m0 = -1e30f, m1 = -1e30f;
            #pragma unroll
            for (int t = 0; t < ST; t++) {
                m0 = fmaxf(m0, fmaxf(s[t][0], s[t][1]));
                m1 = fmaxf(m1, fmaxf(s[t][2], s[t][3]));
            }
            m0 = fmaxf(m0, __shfl_xor_sync(0xffffffffu, m0, 1));
            m0 = fmaxf(m0, __shfl_xor_sync(0xffffffffu, m0, 2));
            m1 = fmaxf(m1, __shfl_xor_sync(0xffffffffu, m1, 1));
            m1 = fmaxf(m1, __shfl_xor_sync(0xffffffffu, m1, 2));
            float sum0 = 0.f, sum1 = 0.f;
            #pragma unroll
            for (int t = 0; t < ST; t++) {
                s[t][0] = __expf(s[t][0] - m0); s[t][1] = __expf(s[t][1] - m0);
                s[t][2] = __expf(s[t][2] - m1); s[t][3] = __expf(s[t][3] - m1);
                sum0 += s[t][0] + s[t][1];
                sum1 += s[t][2] + s[t][3];
            }
            sum0 += __shfl_xor_sync(0xffffffffu, sum0, 1);
            sum0 += __shfl_xor_sync(0xffffffffu, sum0, 2);
            sum1 += __shfl_xor_sync(0xffffffffu, sum1, 1);
            sum1 += __shfl_xor_sync(0xffffffffu, sum1, 2);
            float inv0 = 1.f / sum0, inv1 = 1.f / sum1;
            uint32_t pa[KS][4];
            #pragma unroll
            for (int ph = 0; ph < KS; ph++) {
                int t0 = 2*ph, t1 = 2*ph + 1;
                pa[ph][0] = h2_u32(__floats2half2_rn(s[t0][0]*inv0, s[t0][1]*inv0));
                pa[ph][1] = h2_u32(__floats2half2_rn(s[t0][2]*inv1, s[t0][3]*inv1));
                pa[ph][2] = h2_u32(__floats2half2_rn(s[t1][0]*inv0, s[t1][1]*inv0));
                pa[ph][3] = h2_u32(__floats2half2_rn(s[t1][2]*inv1, s[t1][3]*inv1));
            }
            float oa[4][4];
            #pragma unroll
            for (int nt = 0; nt < 4; nt++) { oa[nt][0]=0.f; oa[nt][1]=0.f; oa[nt][2]=0.f; oa[nt][3]=0.f; }
            #pragma unroll
            for (int ksi = 0; ksi < KS; ksi++) {
                #pragma unroll
                for (int nt = 0; nt < 4; nt++) {
                    uint32_t b[2];
                    uint32_t addr = uv + (nt*8 + (lane & 7))*VROWB + (ksi*16 + ((lane >> 3) & 1)*8)*2;
                    asm volatile("ldmatrix.sync.aligned.m8n8.x2.shared.b16 {%0,%1}, [%2];"
                        : "=r"(b[0]), "=r"(b[1]) : "r"(addr));
                    asm volatile(
                        "mma.sync.aligned.m16n8k16.row.col.f32.f16.f16.f32 "
                        "{%0,%1,%2,%3}, {%4,%5,%6,%7}, {%8,%9}, {%0,%1,%2,%3};"
                        : "+f"(oa[nt][0]), "+f"(oa[nt][1]), "+f"(oa[nt][2]), "+f"(oa[nt][3])
                        : "r"(pa[ksi][0]), "r"(pa[ksi][1]), "r"(pa[ksi][2]), "r"(pa[ksi][3]),
                          "r"(b[0]), "r"(b[1]));
                }
            }
            if (row0 < NT) {
                #pragma unroll
                for (int nt = 0; nt < 4; nt++)
                    *(__half2*)&o[(size_t)(tokbase + row0)*DIMV + h*DHEAD + nt*8 + tig*2] =
                        __floats2half2_rn(oa[nt][0], oa[nt][1]);
            }
            if (row0 + 8 < NT) {
                #pragma unroll
                for (int nt = 0; nt < 4; nt++)
                    *(__half2*)&o[(size_t)(tokbase + row0 + 8)*DIMV + h*DHEAD + nt*8 + tig*2] =
                        __floats2half2_rn(oa[nt][2], oa[nt][3]);
            }
        }
        __syncwarp();
    }
}

#define ATTN_SMEM_65 (8 * ((80*80) + (80*80) + 32*(80*2+16)))
#define ATTN_SMEM_64 (8 * ((64*80) + (64*80) + 32*(64*2+16)))

// ================= fp16 GEMM: BM=128 BN=64 BK=32, 32x32 warp tiles, 3 CTAs/SM =================
#define BM 128
#define BN 64
#define BK 32
#define NSTG 3
#define ROWB 80
#define STG_BYTES ((BM + BN) * ROWB)   // 15360
#define SMEM_GEMM (NSTG * STG_BYTES)   // 46080

__global__ __launch_bounds__(256, 3) void gemm_mma(
    const __half* __restrict__ A, const __half* __restrict__ B,
    const float* __restrict__ bias, float* __restrict__ C,
    __half* __restrict__ Oh, int N, int K, int epi, int cs)
{
    extern __shared__ char smem[];
    const uint32_t sb = smem_to_u32(smem);
    const int tid = threadIdx.x;
    const int bm = blockIdx.y * BM;
    const int bn = blockIdx.x * BN;
    const int total = K / BK;

    const int wid = tid >> 5, lane = tid & 31;
    const int wm = wid & 3, wn = wid >> 2;   // 4(M) x 2(N) warps, 32x32 tiles

    float acc[2][4][4];
    #pragma unroll
    for (int mi = 0; mi < 2; mi++)
        #pragma unroll
        for (int ni = 0; ni < 4; ni++)
            #pragma unroll
            for (int r = 0; r < 4; r++) acc[mi][ni][r] = 0.f;

    auto load_chunk = [&](int c) {
        int col = c*BK;
        uint32_t stA = sb + (c % NSTG) * STG_BYTES;
        uint32_t stB = stA + BM * ROWB;
        #pragma unroll
        for (int i = 0; i < 2; i++) {                 // A: 128 rows x 4 segs
            int s = tid + i*256;
            int row = s >> 2, seg = s & 3;
            cp16(stA + row*ROWB + seg*16, A + (size_t)(bm + row)*K + col + seg*8);
        }
        {                                             // B: 64 rows x 4 segs
            int row = tid >> 2, seg = tid & 3;
            cp16(stB + row*ROWB + seg*16, B + (size_t)(bn + row)*K + col + seg*8);
        }
        cp_commit();
    };

    load_chunk(0);
    load_chunk(1);

    for (int c = 0; c < total; c++) {
        if (c == total - 1) asm volatile("cp.async.wait_group 0;\n" ::: "memory");
        else                asm volatile("cp.async.wait_group 1;\n" ::: "memory");
        __syncthreads();
        if (c + 2 < total) load_chunk(c + 2);

        uint32_t stA = sb + (c % NSTG) * STG_BYTES;
        uint32_t stB = stA + BM * ROWB;
        #pragma unroll
        for (int ks = 0; ks < 2; ks++) {
            uint32_t a[2][4];
            #pragma unroll
            for (int mi = 0; mi < 2; mi++) {
                uint32_t addr = stA + (wm*32 + mi*16 + (lane & 15))*ROWB + ((lane >> 4)*16 + ks*32);
                asm volatile("ldmatrix.sync.aligned.m8n8.x4.shared.b16 {%0,%1,%2,%3}, [%4];"
                    : "=r"(a[mi][0]), "=r"(a[mi][1]), "=r"(a[mi][2]), "=r"(a[mi][3]) : "r"(addr));
            }
            uint32_t b[4][2];
            #pragma unroll
            for (int nb = 0; nb < 2; nb++) {
                uint32_t r0, r1, r2, r3;
                uint32_t addr = stB + (wn*32 + nb*16 + (lane & 15))*ROWB + ((lane >> 4)*16 + ks*32);
                asm volatile("ldmatrix.sync.aligned.m8n8.x4.shared.b16 {%0,%1,%2,%3}, [%4];"
                    : "=r"(r0), "=r"(r1), "=r"(r2), "=r"(r3) : "r"(addr));
                b[nb*2][0]   = r0; b[nb*2][1]   = r2;
                b[nb*2+1][0] = r1; b[nb*2+1][1] = r3;
            }
            #pragma unroll
            for (int mi = 0; mi < 2; mi++)
                #pragma unroll
                for (int ni = 0; ni < 4; ni++) {
                    asm volatile(
                        "mma.sync.aligned.m16n8k16.row.col.f32.f16.f16.f32 "
                        "{%0,%1,%2,%3}, {%4,%5,%6,%7}, {%8,%9}, {%0,%1,%2,%3};"
                        : "+f"(acc[mi][ni][0]), "+f"(acc[mi][ni][1]),
                          "+f"(acc[mi][ni][2]), "+f"(acc[mi][ni][3])
                        : "r"(a[mi][0]), "r"(a[mi][1]), "r"(a[mi][2]), "r"(a[mi][3]),
                          "r"(b[ni][0]), "r"(b[ni][1]));
                }
        }
    }

    // ---- epilogue ----
    const int g = lane >> 2, tig = lane & 3;
    #pragma unroll
    for (int mi = 0; mi < 2; mi++) {
        #pragma unroll
        for (int ni = 0; ni < 4; ni++) {
            int r0 = bm + wm*32 + mi*16 + g;
            int cc = bn + wn*32 + ni*8 + tig*2;
            #pragma unroll
            for (int half = 0; half < 2; half++) {
                int r = r0 + half*8;
                float v0 = acc[mi][ni][half*2 + 0];
                float v1 = acc[mi][ni][half*2 + 1];
                if (epi == 0) {
                    float2 st; st.x = v0; st.y = v1;
                    *(float2*)&C[(size_t)r*cs + cc] = st;
                } else if (epi == 1) {
                    float2 bi  = *(const float2*)&bias[cc];
                    float2 res = *(const float2*)&C[(size_t)r*cs + cc];
                    float2 st; st.x = v0 + bi.x + res.x; st.y = v1 + bi.y + res.y;
                    *(float2*)&C[(size_t)r*cs + cc] = st;
                } else if (epi == 2) {
                    float2 bi = *(const float2*)&bias[cc];
                    float g0 = gelu_exact(v0 + bi.x);
                    float g1 = gelu_exact(v1 + bi.y);
                    *(__half2*)&Oh[(size_t)r*cs + cc] = __floats2half2_rn(g0, g1);
                } else {
                    *(__half2*)&Oh[(size_t)r*cs + cc] = __floats2half2_rn(v0, v1);
                }
            }
        }
    }
}

// ================= Host driver =================
extern "C" void kernel_launch(void* const* d_in, const int* in_sizes, int n_in,
                              void* d_out, int out_size) {
    const float* local_t  = (const float*)d_in[0];
    const float* region_t = (const float*)d_in[1];
    const float* emb      = (const float*)d_in[2];
    const float* attn_g   = (const float*)d_in[3];
    const float* attn_b   = (const float*)d_in[4];
    const float* wqkv     = (const float*)d_in[5];
    const float* wout     = (const float*)d_in[6];
    const float* bout     = (const float*)d_in[7];
    const float* mlp_g    = (const float*)d_in[8];
    const float* mlp_b    = (const float*)d_in[9];
    const float* w1       = (const float*)d_in[10];
    const float* b1       = (const float*)d_in[11];
    const float* w2       = (const float*)d_in[12];
    const float* b2       = (const float*)d_in[13];
    float* out = (float*)d_out;

    cudaFuncSetAttribute(gemm_mma, cudaFuncAttributeMaxDynamicSharedMemorySize, SMEM_GEMM);
    cudaFuncSetAttribute(attn_tc<NTOK>, cudaFuncAttributeMaxDynamicSharedMemorySize, ATTN_SMEM_65);
    cudaFuncSetAttribute(attn_tc<64>,   cudaFuncAttributeMaxDynamicSharedMemorySize, ATTN_SMEM_64);

    float *xw, *biasT;
    __half *h, *o, *m1, *hr, *orr, *qkv, *qkvr, *Wqkv, *Wout, *W1h, *W2h;
    cudaGetSymbolAddress((void**)&xw,   g_xw);
    cudaGetSymbolAddress((void**)&h,    g_h);
    cudaGetSymbolAddress((void**)&qkv,  g_qkv);
    cudaGetSymbolAddress((void**)&o,    g_o);
    cudaGetSymbolAddress((void**)&m1,   g_m1);
    cudaGetSymbolAddress((void**)&biasT,g_bias);
    cudaGetSymbolAddress((void**)&hr,   g_hr);
    cudaGetSymbolAddress((void**)&qkvr, g_qkvr);
    cudaGetSymbolAddress((void**)&orr,  g_or);
    cudaGetSymbolAddress((void**)&Wqkv, g_Wqkv);
    cudaGetSymbolAddress((void**)&Wout, g_Wout);
    cudaGetSymbolAddress((void**)&W1h,  g_W1h);
    cudaGetSymbolAddress((void**)&W2h,  g_W2h);

    pack_kernel<<<(NROWS*DIMV + 255)/256, 256>>>(local_t, region_t);
    wconv_all<<<T_W2 + BIAS_BLKS, 256>>>(wqkv, wout, w1, w2, emb);

    for (int l = 0; l < DEPTH; l++) {
        __half* WqT = Wqkv + (size_t)l*SEG_QKV;
        __half* WoT = Wout + (size_t)l*SEG_OUT;
        __half* W1T = W1h + (size_t)l*SEG_W1;
        __half* W2T = W2h + (size_t)l*SEG_W2;
        const float* Bout = bout + (size_t)l*DIMV;
        const float* B1   = b1   + (size_t)l*4*DIMV;
        const float* B2   = b2   + (size_t)l*DIMV;
        const float* Ag   = attn_g + (size_t)l*DIMV;
        const float* Ab   = attn_b + (size_t)l*DIMV;
        const float* Mg   = mlp_g  + (size_t)l*DIMV;
        const float* Mb   = mlp_b  + (size_t)l*DIMV;

        // ---- region self-attention ----
        ln_half<<<NWIN/8, 256>>>(xw, NTOK*DIMV, Ag, Ab, hr);
        gemm_mma<<<dim3(3*DIMV/BN, NWIN/BM), 256, SMEM_GEMM>>>(
            hr, WqT, nullptr, nullptr, qkvr, 3*DIMV, DIMV, 3, 3*DIMV);
        attn_tc<64><<<NB, 256, ATTN_SMEM_64>>>(qkvr, nullptr, orr);
        gemm_mma<<<dim3(DIMV/BN, NWIN/BM), 256, SMEM_GEMM>>>(
            orr, WoT, Bout, xw, nullptr, DIMV, DIMV, 1, NTOK*DIMV);

        // ---- window attention ----
        ln_half<<<NROWS/8, 256>>>(xw, DIMV, Ag, Ab, h);
        gemm_mma<<<dim3(3*DIMV/BN, NROWS/BM), 256, SMEM_GEMM>>>(
            h, WqT, nullptr, nullptr, qkv, 3*DIMV, DIMV, 3, 3*DIMV);
        attn_tc<NTOK><<<NWIN, 256, ATTN_SMEM_65>>>(qkv, biasT, o);
        gemm_mma<<<dim3(DIMV/BN, NROWS/BM), 256, SMEM_GEMM>>>(
            o, WoT, Bout, xw, nullptr, DIMV, DIMV, 1, DIMV);

        // ---- MLP ----
        ln_half<<<NROWS/8, 256>>>(xw, DIMV, Mg, Mb, h);
        gemm_mma<<<dim3(4*DIMV/BN, NROWS/BM), 256, SMEM_GEMM>>>(
            h, W1T, B1, nullptr, m1, 4*DIMV, DIMV, 2, 4*DIMV);
        gemm_mma<<<dim3(DIMV/BN, NROWS/BM), 256, SMEM_GEMM>>>(
            m1, W2T, B2, xw, nullptr, DIMV, 4*DIMV, 1, DIMV);
    }

    unpack_kernel<<<(NROWS*DIMV + 255)/256, 256>>>(out);
}

// round 15
// speedup vs baseline: 1.1364x; 1.1364x over previous
#include <cuda_runtime.h>
#include <cuda_fp16.h>
#include <math.h>
#include <stdint.h>

// ---------------- Problem constants ----------------
#define DIMV    512
#define HEADS   16
#define DHEAD   32
#define NWIN    512
#define NTOK    65
#define NROWS   (NWIN*NTOK)  // 33280
#define NB      8
#define DEPTH   4
#define QSCALE  0.17677669529663687f
#define LOCAL_ELEMS (8*64*64*512)

// ---------------- helpers ----------------
__device__ __forceinline__ uint32_t smem_to_u32(const void* p) {
    uint32_t a;
    asm("{ .reg .u64 t; cvta.to.shared.u64 t, %1; cvt.u32.u64 %0, t; }" : "=r"(a) : "l"(p));
    return a;
}
__device__ __forceinline__ void cp16(uint32_t dst, const void* src) {
    asm volatile("cp.async.cg.shared.global [%0], [%1], 16;\n" :: "r"(dst), "l"(src));
}
__device__ __forceinline__ void cp_commit() { asm volatile("cp.async.commit_group;\n" ::: "memory"); }
__device__ __forceinline__ float gelu_exact(float x) {
    return 0.5f * x * (1.0f + erff(x * 0.70710678118654752f));
}
__device__ __forceinline__ uint32_t h2_u32(__half2 v) {
    return *(uint32_t*)&v;
}

// ================= Scratch =================
__device__ __align__(16) float  g_xw  [NROWS*DIMV];
__device__ __align__(16) __half g_h   [NROWS*DIMV];
__device__ __align__(16) __half g_qkv [NROWS*3*DIMV];
__device__ __align__(16) __half g_o   [NROWS*DIMV];
__device__ __align__(16) __half g_m1  [NROWS*4*DIMV];
__device__ __align__(16) float  g_bias[HEADS*NTOK*NTOK];
__device__ __align__(16) __half g_hr  [NWIN*DIMV];
__device__ __align__(16) __half g_qkvr[NWIN*3*DIMV];
__device__ __align__(16) __half g_or  [NWIN*DIMV];
__device__ __align__(16) __half g_Wqkv[DEPTH*3*DIMV*DIMV];
__device__ __align__(16) __half g_Wout[DEPTH*DIMV*DIMV];
__device__ __align__(16) __half g_W1h [DEPTH*4*DIMV*DIMV];
__device__ __align__(16) __half g_W2h [DEPTH*DIMV*4*DIMV];

// ================= pack / unpack (float4-vectorized) =================
__global__ void pack_kernel(const float* __restrict__ local_t, const float* __restrict__ region_t) {
    int idx = blockIdx.x * blockDim.x + threadIdx.x;   // over NROWS*128 float4s
    if (idx >= NROWS*128) return;
    int d4 = idx & 127, row = idx >> 7;
    int win = row / NTOK, t = row - win*NTOK;
    float4 v;
    if (t == 0) v = ((const float4*)region_t)[win*128 + d4];
    else {
        int a = t - 1, p1 = a >> 3, p2 = a & 7;
        int b = win >> 6, rh = (win >> 3) & 7, rw = win & 7;
        v = ((const float4*)local_t)[(((b*64) + (rh*8 + p1))*64 + (rw*8 + p2))*128 + d4];
    }
    ((float4*)g_xw)[idx] = v;
}

__global__ void unpack_kernel(float* __restrict__ out) {
    int idx = blockIdx.x * blockDim.x + threadIdx.x;   // over NROWS*128 float4s
    if (idx >= NROWS*128) return;
    if (idx < LOCAL_ELEMS/4) {
        int d4 = idx & 127, p = idx >> 7;
        int col = p & 63, rowi = (p >> 6) & 63, b = p >> 12;
        int rh = rowi >> 3, p1 = rowi & 7, rw = col >> 3, p2 = col & 7;
        int win = b*64 + rh*8 + rw, t = 1 + p1*8 + p2;
        ((float4*)out)[idx] = ((const float4*)g_xw)[(win*NTOK + t)*128 + d4];
    } else {
        int r = idx - LOCAL_ELEMS/4, w = r >> 7, d4 = r & 127;
        ((float4*)out)[idx] = ((const float4*)g_xw)[(w*NTOK)*128 + d4];
    }
}

// ---- coalesced weight conversion: 32x32 tiled transpose + bias table (R14-proven) ----
#define SEG_QKV (3*DIMV*DIMV)
#define SEG_OUT (DIMV*DIMV)
#define SEG_W1  (DIMV*4*DIMV)
#define SEG_W2  (4*DIMV*DIMV)
#define BIAS_N  (HEADS*NTOK*NTOK)
#define T_QKV 3072
#define T_OUT (T_QKV + 1024)
#define T_W1  (T_OUT + 4096)
#define T_W2  (T_W1 + 4096)   // 12288
#define BIAS_BLKS ((BIAS_N + 255)/256)

__global__ __launch_bounds__(256) void wconv_all(
    const float* __restrict__ wqkv, const float* __restrict__ wout,
    const float* __restrict__ w1, const float* __restrict__ w2,
    const float* __restrict__ emb)
{
    int bid = blockIdx.x;
    if (bid < T_W2) {
        const float* W; __half* O; int K, N, r;
        if (bid < T_QKV) {
            int l = bid / 768; r = bid - l*768;
            W = wqkv + (size_t)l*SEG_QKV; O = g_Wqkv + (size_t)l*SEG_QKV; K = DIMV; N = 3*DIMV;
        } else if (bid < T_OUT) {
            int q = bid - T_QKV; int l = q / 256; r = q - l*256;
            W = wout + (size_t)l*SEG_OUT; O = g_Wout + (size_t)l*SEG_OUT; K = DIMV; N = DIMV;
        } else if (bid < T_W1) {
            int q = bid - T_OUT; int l = q / 1024; r = q - l*1024;
            W = w1 + (size_t)l*SEG_W1; O = g_W1h + (size_t)l*SEG_W1; K = DIMV; N = 4*DIMV;
        } else {
            int q = bid - T_W1; int l = q / 1024; r = q - l*1024;
            W = w2 + (size_t)l*SEG_W2; O = g_W2h + (size_t)l*SEG_W2; K = 4*DIMV; N = DIMV;
        }
        int tilesN = N >> 5;
        int tk = r / tilesN, tn = r - tk*tilesN;
        int k0 = tk*32, n0 = tn*32;
        __shared__ float tile[32][33];
        int tx = threadIdx.x & 31, ty = threadIdx.x >> 5;
        #pragma unroll
        for (int i = 0; i < 4; i++)
            tile[ty + i*8][tx] = W[(size_t)(k0 + ty + i*8)*N + n0 + tx];
        __syncthreads();
        #pragma unroll
        for (int i = 0; i < 4; i++)
            O[(size_t)(n0 + ty + i*8)*K + k0 + tx] = __float2half_rn(tile[tx][ty + i*8]);
    } else {
        int r = (bid - T_W2)*256 + threadIdx.x;
        if (r >= BIAS_N) return;
        int h = r / (NTOK*NTOK);
        int q = r - h*NTOK*NTOK;
        int i = q / NTOK, j = q - i*NTOK;
        float v = 0.f;
        if (i > 0 && j > 0) {
            int a = i - 1, b = j - 1;
            int r0 = (a >> 3) - (b >> 3) + 7;
            int r1 = (a & 7) - (b & 7) + 7;
            v = emb[(r0 + r1*15)*HEADS + h];
        }
        g_bias[r] = v;
    }
}

// ================= LayerNorm -> fp16, warp-per-row =================
__global__ __launch_bounds__(256) void ln_half(const float* __restrict__ x, int instr,
                                               const float* __restrict__ g,
                                               const float* __restrict__ b,
                                               __half* __restrict__ y) {
    int w = threadIdx.x >> 5, lane = threadIdx.x & 31;
    int row = blockIdx.x*8 + w;
    const float4* xv = (const float4*)(x + (size_t)row*instr);
    float4 v[4];
    float s = 0.f, s2 = 0.f;
    #pragma unroll
    for (int i = 0; i < 4; i++) {
        v[i] = xv[lane + 32*i];
        s  += v[i].x + v[i].y + v[i].z + v[i].w;
        s2 += v[i].x*v[i].x + v[i].y*v[i].y + v[i].z*v[i].z + v[i].w*v[i].w;
    }
    #pragma unroll
    for (int off = 16; off; off >>= 1) {
        s  += __shfl_xor_sync(0xffffffffu, s,  off);
        s2 += __shfl_xor_sync(0xffffffffu, s2, off);
    }
    float mean = s * (1.f/512.f);
    float var  = s2 * (1.f/512.f) - mean*mean;
    float rstd = rsqrtf(var + 1e-3f);
    __half2* p = (__half2*)(y + (size_t)row*DIMV);
    #pragma unroll
    for (int i = 0; i < 4; i++) {
        float4 gg = ((const float4*)g)[lane + 32*i];
        float4 bb = ((const float4*)b)[lane + 32*i];
        __half2 o01 = __floats2half2_rn((v[i].x - mean)*rstd*gg.x + bb.x, (v[i].y - mean)*rstd*gg.y + bb.y);
        __half2 o23 = __floats2half2_rn((v[i].z - mean)*rstd*gg.z + bb.z, (v[i].w - mean)*rstd*gg.w + bb.w);
        p[(lane + 32*i)*2]     = o01;
        p[(lane + 32*i)*2 + 1] = o23;
    }
}

// ================= Tensor-core attention (R11 proven) =================
template<int NT>
__global__ __launch_bounds__(256) void attn_tc(const __half* __restrict__ qkv,
                                               const float* __restrict__ biasTab,
                                               __half* __restrict__ o) {
    constexpr int TOK_PAD = (NT + 15) & ~15;
    constexpr int ST = TOK_PAD / 8;
    constexpr int QB = TOK_PAD / 16;
    constexpr int KS = TOK_PAD / 16;
    constexpr int QROWB = 80, KROWB = 80, VROWB = TOK_PAD*2 + 16;
    constexpr int PW = TOK_PAD*QROWB + TOK_PAD*KROWB + 32*VROWB;
    extern __shared__ __align__(16) char smattn[];
    const int w = threadIdx.x >> 5, lane = threadIdx.x & 31;
    char* spq = smattn + w * PW;
    char* spk = spq + TOK_PAD*QROWB;
    char* spv = spk + TOK_PAD*KROWB;
    const uint32_t uq = smem_to_u32(spq);
    const uint32_t uk = smem_to_u32(spk);
    const uint32_t uv = smem_to_u32(spv);
    const int tokbase = blockIdx.x * NT;
    const int g = lane >> 2, tig = lane & 3;

    for (int hh = 0; hh < 2; hh++) {
        const int h = w*2 + hh;
        for (int p = lane; p < NT*16; p += 32) {
            int tok = p >> 4, d2 = p & 15;
            const __half2* src = (const __half2*)(qkv + (size_t)(tokbase + tok)*(3*DIMV) + h*DHEAD + d2*2);
            __half2 qv = src[0];
            float2 qf = __half22float2(qv);
            *(__half2*)(spq + tok*QROWB + d2*4) = __floats2half2_rn(qf.x*QSCALE, qf.y*QSCALE);
            *(__half2*)(spk + tok*KROWB + d2*4) = src[DIMV/2];
            __half2 vv = src[DIMV];
            *(__half*)(spv + (2*d2)*VROWB   + tok*2) = __low2half(vv);
            *(__half*)(spv + (2*d2+1)*VROWB + tok*2) = __high2half(vv);
        }
        if (TOK_PAD > NT) {
            for (int p = lane; p < 32*(TOK_PAD - NT); p += 32) {
                int d = p / (TOK_PAD - NT), c = p - d*(TOK_PAD - NT);
                *(__half*)(spv + d*VROWB + (NT + c)*2) = __ushort_as_half(0);
            }
        }
        __syncwarp();

        for (int qb = 0; qb < QB; qb++) {
            uint32_t afr[2][4];
            #pragma unroll
            for (int kk = 0; kk < 2; kk++) {
                uint32_t addr = uq + (qb*16 + (lane & 15))*QROWB + (lane >> 4)*16 + kk*32;
                asm volatile("ldmatrix.sync.aligned.m8n8.x4.shared.b16 {%0,%1,%2,%3}, [%4];"
                    : "=r"(afr[kk][0]), "=r"(afr[kk][1]), "=r"(afr[kk][2]), "=r"(afr[kk][3]) : "r"(addr));
            }
            float s[ST][4];
            #pragma unroll
            for (int t = 0; t < ST; t++) { s[t][0]=0.f; s[t][1]=0.f; s[t][2]=0.f; s[t][3]=0.f; }
            #pragma unroll
            for (int t = 0; t < ST; t++) {
                #pragma unroll
                for (int kk = 0; kk < 2; kk++) {
                    uint32_t b[2];
                    uint32_t addr = uk + (t*8 + (lane & 7))*KROWB + ((lane >> 3) & 1)*16 + kk*32;
                    asm volatile("ldmatrix.sync.aligned.m8n8.x2.shared.b16 {%0,%1}, [%2];"
                        : "=r"(b[0]), "=r"(b[1]) : "r"(addr));
                    asm volatile(
                        "mma.sync.aligned.m16n8k16.row.col.f32.f16.f16.f32 "
                        "{%0,%1,%2,%3}, {%4,%5,%6,%7}, {%8,%9}, {%0,%1,%2,%3};"
                        : "+f"(s[t][0]), "+f"(s[t][1]), "+f"(s[t][2]), "+f"(s[t][3])
                        : "r"(afr[kk][0]), "r"(afr[kk][1]), "r"(afr[kk][2]), "r"(afr[kk][3]),
                          "r"(b[0]), "r"(b[1]));
                }
            }
            const int row0 = qb*16 + g;
            #pragma unroll
            for (int t = 0; t < ST; t++) {
                int c0 = t*8 + tig*2;
                if (biasTab) {
                    if (row0 < NT) {
                        if (c0 < NT)     s[t][0] += biasTab[(h*NT + row0)*NT + c0];
                        if (c0 + 1 < NT) s[t][1] += biasTab[(h*NT + row0)*NT + c0 + 1];
                    }
                    if (row0 + 8 < NT) {
                        if (c0 < NT)     s[t][2] += biasTab[(h*NT + row0 + 8)*NT + c0];
                        if (c0 + 1 < NT) s[t][3] += biasTab[(h*NT + row0 + 8)*NT + c0 + 1];
                    }
                }
                if (c0 >= NT)     { s[t][0] = -1e30f; s[t][2] = -1e30f; }
                if (c0 + 1 >= NT) { s[t][1] = -1e30f; s[t][3] = -1e30f; }
            }
            float m0 = -1e30f, m1 = -1e30f;
            #pragma unroll
            for (int t = 0; t < ST; t++) {
                m0 = fmaxf(m0, fmaxf(s[t][0], s[t][1]));
                m1 = fmaxf(m1, fmaxf(s[t][2], s[t][3]));
            }
            m0 = fmaxf(m0, __shfl_xor_sync(0xffffffffu, m0, 1));
            m0 = fmaxf(m0, __shfl_xor_sync(0xffffffffu, m0, 2));
            m1 = fmaxf(m1, __shfl_xor_sync(0xffffffffu, m1, 1));
            m1 = fmaxf(m1, __shfl_xor_sync(0xffffffffu, m1, 2));
            float sum0 = 0.f, sum1 = 0.f;
            #pragma unroll
            for (int t = 0; t < ST; t++) {
                s[t][0] = __expf(s[t][0] - m0); s[t][1] = __expf(s[t][1] - m0);
                s[t][2] = __expf(s[t][2] - m1); s[t][3] = __expf(s[t][3] - m1);
                sum0 += s[t][0] + s[t][1];
                sum1 += s[t][2] + s[t][3];
            }
            sum0 += __shfl_xor_sync(0xffffffffu, sum0, 1);
            sum0 += __shfl_xor_sync(0xffffffffu, sum0, 2);
            sum1 += __shfl_xor_sync(0xffffffffu, sum1, 1);
            sum1 += __shfl_xor_sync(0xffffffffu, sum1, 2);
            float inv0 = 1.f / sum0, inv1 = 1.f / sum1;
            uint32_t pa[KS][4];
            #pragma unroll
            for (int ph = 0; ph < KS; ph++) {
                int t0 = 2*ph, t1 = 2*ph + 1;
                pa[ph][0] = h2_u32(__floats2half2_rn(s[t0][0]*inv0, s[t0][1]*inv0));
                pa[ph][1] = h2_u32(__floats2half2_rn(s[t0][2]*inv1, s[t0][3]*inv1));
                pa[ph][2] = h2_u32(__floats2half2_rn(s[t1][0]*inv0, s[t1][1]*inv0));
                pa[ph][3] = h2_u32(__floats2half2_rn(s[t1][2]*inv1, s[t1][3]*inv1));
            }
            float oa[4][4];
            #pragma unroll
            for (int nt = 0; nt < 4; nt++) { oa[nt][0]=0.f; oa[nt][1]=0.f; oa[nt][2]=0.f; oa[nt][3]=0.f; }
            #pragma unroll
            for (int ksi = 0; ksi < KS; ksi++) {
                #pragma unroll
                for (int nt = 0; nt < 4; nt++) {
                    uint32_t b[2];
                    uint32_t addr = uv + (nt*8 + (lane & 7))*VROWB + (ksi*16 + ((lane >> 3) & 1)*8)*2;
                    asm volatile("ldmatrix.sync.aligned.m8n8.x2.shared.b16 {%0,%1}, [%2];"
                        : "=r"(b[0]), "=r"(b[1]) : "r"(addr));
                    asm volatile(
                        "mma.sync.aligned.m16n8k16.row.col.f32.f16.f16.f32 "
                        "{%0,%1,%2,%3}, {%4,%5,%6,%7}, {%8,%9}, {%0,%1,%2,%3};"
                        : "+f"(oa[nt][0]), "+f"(oa[nt][1]), "+f"(oa[nt][2]), "+f"(oa[nt][3])
                        : "r"(pa[ksi][0]), "r"(pa[ksi][1]), "r"(pa[ksi][2]), "r"(pa[ksi][3]),
                          "r"(b[0]), "r"(b[1]));
                }
            }
            if (row0 < NT) {
                #pragma unroll
                for (int nt = 0; nt < 4; nt++)
                    *(__half2*)&o[(size_t)(tokbase + row0)*DIMV + h*DHEAD + nt*8 + tig*2] =
                        __floats2half2_rn(oa[nt][0], oa[nt][1]);
            }
            if (row0 + 8 < NT) {
                #pragma unroll
                for (int nt = 0; nt < 4; nt++)
                    *(__half2*)&o[(size_t)(tokbase + row0 + 8)*DIMV + h*DHEAD + nt*8 + tig*2] =
                        __floats2half2_rn(oa[nt][2], oa[nt][3]);
            }
        }
        __syncwarp();
    }
}

#define ATTN_SMEM_65 (8 * ((80*80) + (80*80) + 32*(80*2+16)))
#define ATTN_SMEM_64 (8 * ((64*80) + (64*80) + 32*(64*2+16)))

// ================= fp16 GEMM (R13-proven: BK=64, 3-stage, 64x32 warps, occ 2) =================
#define BM 128
#define BN 128
#define BK 64
#define NSTG 3
#define ROWB 144
#define STG_BYTES ((BM + BN) * ROWB)
#define SMEM_GEMM (NSTG * STG_BYTES)

__global__ __launch_bounds__(256, 2) void gemm_mma(
    const __half* __restrict__ A, const __half* __restrict__ B,
    const float* __restrict__ bias, float* __restrict__ C,
    __half* __restrict__ Oh, int N, int K, int epi, int cs)
{
    extern __shared__ char smem[];
    const uint32_t sb = smem_to_u32(smem);
    const int tid = threadIdx.x;
    const int bm = blockIdx.y * BM;
    const int bn = blockIdx.x * BN;
    const int total = K / BK;

    const int wid = tid >> 5, lane = tid & 31;
    const int wm = wid & 1, wn = wid >> 1;

    float acc[4][4][4];
    #pragma unroll
    for (int mi = 0; mi < 4; mi++)
        #pragma unroll
        for (int ni = 0; ni < 4; ni++)
            #pragma unroll
            for (int r = 0; r < 4; r++) acc[mi][ni][r] = 0.f;

    auto load_chunk = [&](int c) {
        int col = c*BK;
        uint32_t stA = sb + (c % NSTG) * STG_BYTES;
        uint32_t stB = stA + BM * ROWB;
        #pragma unroll
        for (int i = 0; i < 4; i++) {
            int s = tid + i*256;
            int row = s >> 3, seg = s & 7;
            cp16(stA + row*ROWB + seg*16, A + (size_t)(bm + row)*K + col + seg*8);
            cp16(stB + row*ROWB + seg*16, B + (size_t)(bn + row)*K + col + seg*8);
        }
        cp_commit();
    };

    load_chunk(0);
    load_chunk(1);

    for (int c = 0; c < total; c++) {
        if (c == total - 1) asm volatile("cp.async.wait_group 0;\n" ::: "memory");
        else                asm volatile("cp.async.wait_group 1;\n" ::: "memory");
        __syncthreads();
        if (c + 2 < total) load_chunk(c + 2);

        uint32_t stA = sb + (c % NSTG) * STG_BYTES;
        uint32_t stB = stA + BM * ROWB;
        #pragma unroll
        for (int ks = 0; ks < 4; ks++) {
            uint32_t a[4][4];
            #pragma unroll
            for (int mi = 0; mi < 4; mi++) {
                uint32_t addr = stA + (wm*64 + mi*16 + (lane & 15))*ROWB + ((lane >> 4)*16 + ks*32);
                asm volatile("ldmatrix.sync.aligned.m8n8.x4.shared.b16 {%0,%1,%2,%3}, [%4];"
                    : "=r"(a[mi][0]), "=r"(a[mi][1]), "=r"(a[mi][2]), "=r"(a[mi][3]) : "r"(addr));
            }
            uint32_t b[4][2];
            #pragma unroll
            for (int ni = 0; ni < 4; ni++) {
                uint32_t addr = stB + (wn*32 + ni*8 + (lane & 7))*ROWB + (((lane >> 3) & 1)*16 + ks*32);
                asm volatile("ldmatrix.sync.aligned.m8n8.x2.shared.b16 {%0,%1}, [%2];"
                    : "=r"(b[ni][0]), "=r"(b[ni][1]) : "r"(addr));
            }
            #pragma unroll
            for (int mi = 0; mi < 4; mi++)
                #pragma unroll
                for (int ni = 0; ni < 4; ni++) {
                    asm volatile(
                        "mma.sync.aligned.m16n8k16.row.col.f32.f16.f16.f32 "
                        "{%0,%1,%2,%3}, {%4,%5,%6,%7}, {%8,%9}, {%0,%1,%2,%3};"
                        : "+f"(acc[mi][ni][0]), "+f"(acc[mi][ni][1]),
                          "+f"(acc[mi][ni][2]), "+f"(acc[mi][ni][3])
                        : "r"(a[mi][0]), "r"(a[mi][1]), "r"(a[mi][2]), "r"(a[mi][3]),
                          "r"(b[ni][0]), "r"(b[ni][1]));
                }
        }
    }

    // ---- epilogue ----
    const int g = lane >> 2, tig = lane & 3;
    #pragma unroll
    for (int mi = 0; mi < 4; mi++) {
        #pragma unroll
        for (int ni = 0; ni < 4; ni++) {
            int r0 = bm + wm*64 + mi*16 + g;
            int cc = bn + wn*32 + ni*8 + tig*2;
            #pragma unroll
            for (int half = 0; half < 2; half++) {
                int r = r0 + half*8;
                float v0 = acc[mi][ni][half*2 + 0];
                float v1 = acc[mi][ni][half*2 + 1];
                if (epi == 0) {
                    float2 st; st.x = v0; st.y = v1;
                    *(float2*)&C[(size_t)r*cs + cc] = st;
                } else if (epi == 1) {
                    float2 bi  = *(const float2*)&bias[cc];
                    float2 res = *(const float2*)&C[(size_t)r*cs + cc];
                    float2 st; st.x = v0 + bi.x + res.x; st.y = v1 + bi.y + res.y;
                    *(float2*)&C[(size_t)r*cs + cc] = st;
                } else if (epi == 2) {
                    float2 bi = *(const float2*)&bias[cc];
                    float g0 = gelu_exact(v0 + bi.x);
                    float g1 = gelu_exact(v1 + bi.y);
                    *(__half2*)&Oh[(size_t)r*cs + cc] = __floats2half2_rn(g0, g1);
                } else {
                    *(__half2*)&Oh[(size_t)r*cs + cc] = __floats2half2_rn(v0, v1);
                }
            }
        }
    }
}

// ================= Host driver =================
extern "C" void kernel_launch(void* const* d_in, const int* in_sizes, int n_in,
                              void* d_out, int out_size) {
    const float* local_t  = (const float*)d_in[0];
    const float* region_t = (const float*)d_in[1];
    const float* emb      = (const float*)d_in[2];
    const float* attn_g   = (const float*)d_in[3];
    const float* attn_b   = (const float*)d_in[4];
    const float* wqkv     = (const float*)d_in[5];
    const float* wout     = (const float*)d_in[6];
    const float* bout     = (const float*)d_in[7];
    const float* mlp_g    = (const float*)d_in[8];
    const float* mlp_b    = (const float*)d_in[9];
    const float* w1       = (const float*)d_in[10];
    const float* b1       = (const float*)d_in[11];
    const float* w2       = (const float*)d_in[12];
    const float* b2       = (const float*)d_in[13];
    float* out = (float*)d_out;

    cudaFuncSetAttribute(gemm_mma, cudaFuncAttributeMaxDynamicSharedMemorySize, SMEM_GEMM);
    cudaFuncSetAttribute(attn_tc<NTOK>, cudaFuncAttributeMaxDynamicSharedMemorySize, ATTN_SMEM_65);
    cudaFuncSetAttribute(attn_tc<64>,   cudaFuncAttributeMaxDynamicSharedMemorySize, ATTN_SMEM_64);

    float *xw, *biasT;
    __half *h, *o, *m1, *hr, *orr, *qkv, *qkvr, *Wqkv, *Wout, *W1h, *W2h;
    cudaGetSymbolAddress((void**)&xw,   g_xw);
    cudaGetSymbolAddress((void**)&h,    g_h);
    cudaGetSymbolAddress((void**)&qkv,  g_qkv);
    cudaGetSymbolAddress((void**)&o,    g_o);
    cudaGetSymbolAddress((void**)&m1,   g_m1);
    cudaGetSymbolAddress((void**)&biasT,g_bias);
    cudaGetSymbolAddress((void**)&hr,   g_hr);
    cudaGetSymbolAddress((void**)&qkvr, g_qkvr);
    cudaGetSymbolAddress((void**)&orr,  g_or);
    cudaGetSymbolAddress((void**)&Wqkv, g_Wqkv);
    cudaGetSymbolAddress((void**)&Wout, g_Wout);
    cudaGetSymbolAddress((void**)&W1h,  g_W1h);
    cudaGetSymbolAddress((void**)&W2h,  g_W2h);

    pack_kernel<<<(NROWS*128 + 255)/256, 256>>>(local_t, region_t);
    wconv_all<<<T_W2 + BIAS_BLKS, 256>>>(wqkv, wout, w1, w2, emb);

    for (int l = 0; l < DEPTH; l++) {
        __half* WqT = Wqkv + (size_t)l*SEG_QKV;
        __half* WoT = Wout + (size_t)l*SEG_OUT;
        __half* W1T = W1h + (size_t)l*SEG_W1;
        __half* W2T = W2h + (size_t)l*SEG_W2;
        const float* Bout = bout + (size_t)l*DIMV;
        const float* B1   = b1   + (size_t)l*4*DIMV;
        const float* B2   = b2   + (size_t)l*DIMV;
        const float* Ag   = attn_g + (size_t)l*DIMV;
        const float* Ab   = attn_b + (size_t)l*DIMV;
        const float* Mg   = mlp_g  + (size_t)l*DIMV;
        const float* Mb   = mlp_b  + (size_t)l*DIMV;

        // ---- region self-attention ----
        ln_half<<<NWIN/8, 256>>>(xw, NTOK*DIMV, Ag, Ab, hr);
        gemm_mma<<<dim3(3*DIMV/BN, NWIN/BM), 256, SMEM_GEMM>>>(
            hr, WqT, nullptr, nullptr, qkvr, 3*DIMV, DIMV, 3, 3*DIMV);
        attn_tc<64><<<NB, 256, ATTN_SMEM_64>>>(qkvr, nullptr, orr);
        gemm_mma<<<dim3(DIMV/BN, NWIN/BM), 256, SMEM_GEMM>>>(
            orr, WoT, Bout, xw, nullptr, DIMV, DIMV, 1, NTOK*DIMV);

        // ---- window attention ----
        ln_half<<<NROWS/8, 256>>>(xw, DIMV, Ag, Ab, h);
        gemm_mma<<<dim3(3*DIMV/BN, NROWS/BM), 256, SMEM_GEMM>>>(
            h, WqT, nullptr, nullptr, qkv, 3*DIMV, DIMV, 3, 3*DIMV);
        attn_tc<NTOK><<<NWIN, 256, ATTN_SMEM_65>>>(qkv, biasT, o);
        gemm_mma<<<dim3(DIMV/BN, NROWS/BM), 256, SMEM_GEMM>>>(
            o, WoT, Bout, xw, nullptr, DIMV, DIMV, 1, DIMV);

        // ---- MLP ----
        ln_half<<<NROWS/8, 256>>>(xw, DIMV, Mg, Mb, h);
        gemm_mma<<<dim3(4*DIMV/BN, NROWS/BM), 256, SMEM_GEMM>>>(
            h, W1T, B1, nullptr, m1, 4*DIMV, DIMV, 2, 4*DIMV);
        gemm_mma<<<dim3(DIMV/BN, NROWS/BM), 256, SMEM_GEMM>>>(
            m1, W2T, B2, xw, nullptr, DIMV, 4*DIMV, 1, DIMV);
    }

    unpack_kernel<<<(NROWS*128 + 255)/256, 256>>>(out);
}

// round 16
// speedup vs baseline: 1.1676x; 1.0275x over previous
#include <cuda_runtime.h>
#include <cuda_fp16.h>
#include <math.h>
#include <stdint.h>

// ---------------- Problem constants ----------------
#define DIMV    512
#define HEADS   16
#define DHEAD   32
#define NWIN    512
#define NTOK    65
#define NROWS   (NWIN*NTOK)  // 33280
#define NB      8
#define DEPTH   4
#define QSCALE  0.17677669529663687f
#define LOCAL_ELEMS (8*64*64*512)

// ---------------- helpers ----------------
__device__ __forceinline__ uint32_t smem_to_u32(const void* p) {
    uint32_t a;
    asm("{ .reg .u64 t; cvta.to.shared.u64 t, %1; cvt.u32.u64 %0, t; }" : "=r"(a) : "l"(p));
    return a;
}
__device__ __forceinline__ void cp16(uint32_t dst, const void* src) {
    asm volatile("cp.async.cg.shared.global [%0], [%1], 16;\n" :: "r"(dst), "l"(src));
}
__device__ __forceinline__ void cp_commit() { asm volatile("cp.async.commit_group;\n" ::: "memory"); }
__device__ __forceinline__ float gelu_exact(float x) {
    return 0.5f * x * (1.0f + erff(x * 0.70710678118654752f));
}
__device__ __forceinline__ uint32_t h2_u32(__half2 v) {
    return *(uint32_t*)&v;
}

// ================= Scratch =================
__device__ __align__(16) float  g_xw  [NROWS*DIMV];
__device__ __align__(16) __half g_h   [NROWS*DIMV];
__device__ __align__(16) __half g_qkv [NROWS*3*DIMV];
__device__ __align__(16) __half g_o   [NROWS*DIMV];
__device__ __align__(16) __half g_m1  [NROWS*4*DIMV];
__device__ __align__(16) float  g_bias[HEADS*NTOK*NTOK];
__device__ __align__(16) __half g_hr  [NWIN*DIMV];
__device__ __align__(16) __half g_qkvr[NWIN*3*DIMV];
__device__ __align__(16) __half g_or  [NWIN*DIMV];
__device__ __align__(16) __half g_Wqkv[DEPTH*3*DIMV*DIMV];
__device__ __align__(16) __half g_Wout[DEPTH*DIMV*DIMV];
__device__ __align__(16) __half g_W1h [DEPTH*4*DIMV*DIMV];
__device__ __align__(16) __half g_W2h [DEPTH*DIMV*4*DIMV];

// ================= pack (float4-vectorized) =================
__global__ void pack_kernel(const float* __restrict__ local_t, const float* __restrict__ region_t) {
    int idx = blockIdx.x * blockDim.x + threadIdx.x;
    if (idx >= NROWS*128) return;
    int d4 = idx & 127, row = idx >> 7;
    int win = row / NTOK, t = row - win*NTOK;
    float4 v;
    if (t == 0) v = ((const float4*)region_t)[win*128 + d4];
    else {
        int a = t - 1, p1 = a >> 3, p2 = a & 7;
        int b = win >> 6, rh = (win >> 3) & 7, rw = win & 7;
        v = ((const float4*)local_t)[(((b*64) + (rh*8 + p1))*64 + (rw*8 + p2))*128 + d4];
    }
    ((float4*)g_xw)[idx] = v;
}

// ---- coalesced weight conversion: 32x32 tiled transpose + bias table ----
#define SEG_QKV (3*DIMV*DIMV)
#define SEG_OUT (DIMV*DIMV)
#define SEG_W1  (DIMV*4*DIMV)
#define SEG_W2  (4*DIMV*DIMV)
#define BIAS_N  (HEADS*NTOK*NTOK)
#define T_QKV 3072
#define T_OUT (T_QKV + 1024)
#define T_W1  (T_OUT + 4096)
#define T_W2  (T_W1 + 4096)   // 12288
#define BIAS_BLKS ((BIAS_N + 255)/256)

__global__ __launch_bounds__(256) void wconv_all(
    const float* __restrict__ wqkv, const float* __restrict__ wout,
    const float* __restrict__ w1, const float* __restrict__ w2,
    const float* __restrict__ emb)
{
    int bid = blockIdx.x;
    if (bid < T_W2) {
        const float* W; __half* O; int K, N, r;
        if (bid < T_QKV) {
            int l = bid / 768; r = bid - l*768;
            W = wqkv + (size_t)l*SEG_QKV; O = g_Wqkv + (size_t)l*SEG_QKV; K = DIMV; N = 3*DIMV;
        } else if (bid < T_OUT) {
            int q = bid - T_QKV; int l = q / 256; r = q - l*256;
            W = wout + (size_t)l*SEG_OUT; O = g_Wout + (size_t)l*SEG_OUT; K = DIMV; N = DIMV;
        } else if (bid < T_W1) {
            int q = bid - T_OUT; int l = q / 1024; r = q - l*1024;
            W = w1 + (size_t)l*SEG_W1; O = g_W1h + (size_t)l*SEG_W1; K = DIMV; N = 4*DIMV;
        } else {
            int q = bid - T_W1; int l = q / 1024; r = q - l*1024;
            W = w2 + (size_t)l*SEG_W2; O = g_W2h + (size_t)l*SEG_W2; K = 4*DIMV; N = DIMV;
        }
        int tilesN = N >> 5;
        int tk = r / tilesN, tn = r - tk*tilesN;
        int k0 = tk*32, n0 = tn*32;
        __shared__ float tile[32][33];
        int tx = threadIdx.x & 31, ty = threadIdx.x >> 5;
        #pragma unroll
        for (int i = 0; i < 4; i++)
            tile[ty + i*8][tx] = W[(size_t)(k0 + ty + i*8)*N + n0 + tx];
        __syncthreads();
        #pragma unroll
        for (int i = 0; i < 4; i++)
            O[(size_t)(n0 + ty + i*8)*K + k0 + tx] = __float2half_rn(tile[tx][ty + i*8]);
    } else {
        int r = (bid - T_W2)*256 + threadIdx.x;
        if (r >= BIAS_N) return;
        int h = r / (NTOK*NTOK);
        int q = r - h*NTOK*NTOK;
        int i = q / NTOK, j = q - i*NTOK;
        float v = 0.f;
        if (i > 0 && j > 0) {
            int a = i - 1, b = j - 1;
            int r0 = (a >> 3) - (b >> 3) + 7;
            int r1 = (a & 7) - (b & 7) + 7;
            v = emb[(r0 + r1*15)*HEADS + h];
        }
        g_bias[r] = v;
    }
}

// ================= LayerNorm -> fp16, warp-per-row =================
__global__ __launch_bounds__(256) void ln_half(const float* __restrict__ x, int instr,
                                               const float* __restrict__ g,
                                               const float* __restrict__ b,
                                               __half* __restrict__ y) {
    int w = threadIdx.x >> 5, lane = threadIdx.x & 31;
    int row = blockIdx.x*8 + w;
    const float4* xv = (const float4*)(x + (size_t)row*instr);
    float4 v[4];
    float s = 0.f, s2 = 0.f;
    #pragma unroll
    for (int i = 0; i < 4; i++) {
        v[i] = xv[lane + 32*i];
        s  += v[i].x + v[i].y + v[i].z + v[i].w;
        s2 += v[i].x*v[i].x + v[i].y*v[i].y + v[i].z*v[i].z + v[i].w*v[i].w;
    }
    #pragma unroll
    for (int off = 16; off; off >>= 1) {
        s  += __shfl_xor_sync(0xffffffffu, s,  off);
        s2 += __shfl_xor_sync(0xffffffffu, s2, off);
    }
    float mean = s * (1.f/512.f);
    float var  = s2 * (1.f/512.f) - mean*mean;
    float rstd = rsqrtf(var + 1e-3f);
    __half2* p = (__half2*)(y + (size_t)row*DIMV);
    #pragma unroll
    for (int i = 0; i < 4; i++) {
        float4 gg = ((const float4*)g)[lane + 32*i];
        float4 bb = ((const float4*)b)[lane + 32*i];
        __half2 o01 = __floats2half2_rn((v[i].x - mean)*rstd*gg.x + bb.x, (v[i].y - mean)*rstd*gg.y + bb.y);
        __half2 o23 = __floats2half2_rn((v[i].z - mean)*rstd*gg.z + bb.z, (v[i].w - mean)*rstd*gg.w + bb.w);
        p[(lane + 32*i)*2]     = o01;
        p[(lane + 32*i)*2 + 1] = o23;
    }
}

// ================= Tensor-core attention (R11 proven) =================
template<int NT>
__global__ __launch_bounds__(256) void attn_tc(const __half* __restrict__ qkv,
                                               const float* __restrict__ biasTab,
                                               __half* __restrict__ o) {
    constexpr int TOK_PAD = (NT + 15) & ~15;
    constexpr int ST = TOK_PAD / 8;
    constexpr int QB = TOK_PAD / 16;
    constexpr int KS = TOK_PAD / 16;
    constexpr int QROWB = 80, KROWB = 80, VROWB = TOK_PAD*2 + 16;
    constexpr int PW = TOK_PAD*QROWB + TOK_PAD*KROWB + 32*VROWB;
    extern __shared__ __align__(16) char smattn[];
    const int w = threadIdx.x >> 5, lane = threadIdx.x & 31;
    char* spq = smattn + w * PW;
    char* spk = spq + TOK_PAD*QROWB;
    char* spv = spk + TOK_PAD*KROWB;
    const uint32_t uq = smem_to_u32(spq);
    const uint32_t uk = smem_to_u32(spk);
    const uint32_t uv = smem_to_u32(spv);
    const int tokbase = blockIdx.x * NT;
    const int g = lane >> 2, tig = lane & 3;

    for (int hh = 0; hh < 2; hh++) {
        const int h = w*2 + hh;
        for (int p = lane; p < NT*16; p += 32) {
            int tok = p >> 4, d2 = p & 15;
            const __half2* src = (const __half2*)(qkv + (size_t)(tokbase + tok)*(3*DIMV) + h*DHEAD + d2*2);
            __half2 qv = src[0];
            float2 qf = __half22float2(qv);
            *(__half2*)(spq + tok*QROWB + d2*4) = __floats2half2_rn(qf.x*QSCALE, qf.y*QSCALE);
            *(__half2*)(spk + tok*KROWB + d2*4) = src[DIMV/2];
            __half2 vv = src[DIMV];
            *(__half*)(spv + (2*d2)*VROWB   + tok*2) = __low2half(vv);
            *(__half*)(spv + (2*d2+1)*VROWB + tok*2) = __high2half(vv);
        }
        if (TOK_PAD > NT) {
            for (int p = lane; p < 32*(TOK_PAD - NT); p += 32) {
                int d = p / (TOK_PAD - NT), c = p - d*(TOK_PAD - NT);
                *(__half*)(spv + d*VROWB + (NT + c)*2) = __ushort_as_half(0);
            }
        }
        __syncwarp();

        for (int qb = 0; qb < QB; qb++) {
            uint32_t afr[2][4];
            #pragma unroll
            for (int kk = 0; kk < 2; kk++) {
                uint32_t addr = uq + (qb*16 + (lane & 15))*QROWB + (lane >> 4)*16 + kk*32;
                asm volatile("ldmatrix.sync.aligned.m8n8.x4.shared.b16 {%0,%1,%2,%3}, [%4];"
                    : "=r"(afr[kk][0]), "=r"(afr[kk][1]), "=r"(afr[kk][2]), "=r"(afr[kk][3]) : "r"(addr));
            }
            float s[ST][4];
            #pragma unroll
            for (int t = 0; t < ST; t++) { s[t][0]=0.f; s[t][1]=0.f; s[t][2]=0.f; s[t][3]=0.f; }
            #pragma unroll
            for (int t = 0; t < ST; t++) {
                #pragma unroll
                for (int kk = 0; kk < 2; kk++) {
                    uint32_t b[2];
                    uint32_t addr = uk + (t*8 + (lane & 7))*KROWB + ((lane >> 3) & 1)*16 + kk*32;
                    asm volatile("ldmatrix.sync.aligned.m8n8.x2.shared.b16 {%0,%1}, [%2];"
                        : "=r"(b[0]), "=r"(b[1]) : "r"(addr));
                    asm volatile(
                        "mma.sync.aligned.m16n8k16.row.col.f32.f16.f16.f32 "
                        "{%0,%1,%2,%3}, {%4,%5,%6,%7}, {%8,%9}, {%0,%1,%2,%3};"
                        : "+f"(s[t][0]), "+f"(s[t][1]), "+f"(s[t][2]), "+f"(s[t][3])
                        : "r"(afr[kk][0]), "r"(afr[kk][1]), "r"(afr[kk][2]), "r"(afr[kk][3]),
                          "r"(b[0]), "r"(b[1]));
                }
            }
            const int row0 = qb*16 + g;
            #pragma unroll
            for (int t = 0; t < ST; t++) {
                int c0 = t*8 + tig*2;
                if (biasTab) {
                    if (row0 < NT) {
                        if (c0 < NT)     s[t][0] += biasTab[(h*NT + row0)*NT + c0];
                        if (c0 + 1 < NT) s[t][1] += biasTab[(h*NT + row0)*NT + c0 + 1];
                    }
                    if (row0 + 8 < NT) {
                        if (c0 < NT)     s[t][2] += biasTab[(h*NT + row0 + 8)*NT + c0];
                        if (c0 + 1 < NT) s[t][3] += biasTab[(h*NT + row0 + 8)*NT + c0 + 1];
                    }
                }
                if (c0 >= NT)     { s[t][0] = -1e30f; s[t][2] = -1e30f; }
                if (c0 + 1 >= NT) { s[t][1] = -1e30f; s[t][3] = -1e30f; }
            }
            float m0 = -1e30f, m1 = -1e30f;
            #pragma unroll
            for (int t = 0; t < ST; t++) {
                m0 = fmaxf(m0, fmaxf(s[t][0], s[t][1]));
                m1 = fmaxf(m1, fmaxf(s[t][2], s[t][3]));
            }
            m0 = fmaxf(m0, __shfl_xor_sync(0xffffffffu, m0, 1));
            m0 = fmaxf(m0, __shfl_xor_sync(0xffffffffu, m0, 2));
            m1 = fmaxf(m1, __shfl_xor_sync(0xffffffffu, m1, 1));
            m1 = fmaxf(m1, __shfl_xor_sync(0xffffffffu, m1, 2));
            float sum0 = 0.f, sum1 = 0.f;
            #pragma unroll
            for (int t = 0; t < ST; t++) {
                s[t][0] = __expf(s[t][0] - m0); s[t][1] = __expf(s[t][1] - m0);
                s[t][2] = __expf(s[t][2] - m1); s[t][3] = __expf(s[t][3] - m1);
                sum0 += s[t][0] + s[t][1];
                sum1 += s[t][2] + s[t][3];
            }
            sum0 += __shfl_xor_sync(0xffffffffu, sum0, 1);
            sum0 += __shfl_xor_sync(0xffffffffu, sum0, 2);
            sum1 += __shfl_xor_sync(0xffffffffu, sum1, 1);
            sum1 += __shfl_xor_sync(0xffffffffu, sum1, 2);
            float inv0 = 1.f / sum0, inv1 = 1.f / sum1;
            uint32_t pa[KS][4];
            #pragma unroll
            for (int ph = 0; ph < KS; ph++) {
                int t0 = 2*ph, t1 = 2*ph + 1;
                pa[ph][0] = h2_u32(__floats2half2_rn(s[t0][0]*inv0, s[t0][1]*inv0));
                pa[ph][1] = h2_u32(__floats2half2_rn(s[t0][2]*inv1, s[t0][3]*inv1));
                pa[ph][2] = h2_u32(__floats2half2_rn(s[t1][0]*inv0, s[t1][1]*inv0));
                pa[ph][3] = h2_u32(__floats2half2_rn(s[t1][2]*inv1, s[t1][3]*inv1));
            }
            float oa[4][4];
            #pragma unroll
            for (int nt = 0; nt < 4; nt++) { oa[nt][0]=0.f; oa[nt][1]=0.f; oa[nt][2]=0.f; oa[nt][3]=0.f; }
            #pragma unroll
            for (int ksi = 0; ksi < KS; ksi++) {
                #pragma unroll
                for (int nt = 0; nt < 4; nt++) {
                    uint32_t b[2];
                    uint32_t addr = uv + (nt*8 + (lane & 7))*VROWB + (ksi*16 + ((lane >> 3) & 1)*8)*2;
                    asm volatile("ldmatrix.sync.aligned.m8n8.x2.shared.b16 {%0,%1}, [%2];"
                        : "=r"(b[0]), "=r"(b[1]) : "r"(addr));
                    asm volatile(
                        "mma.sync.aligned.m16n8k16.row.col.f32.f16.f16.f32 "
                        "{%0,%1,%2,%3}, {%4,%5,%6,%7}, {%8,%9}, {%0,%1,%2,%3};"
                        : "+f"(oa[nt][0]), "+f"(oa[nt][1]), "+f"(oa[nt][2]), "+f"(oa[nt][3])
                        : "r"(pa[ksi][0]), "r"(pa[ksi][1]), "r"(pa[ksi][2]), "r"(pa[ksi][3]),
                          "r"(b[0]), "r"(b[1]));
                }
            }
            if (row0 < NT) {
                #pragma unroll
                for (int nt = 0; nt < 4; nt++)
                    *(__half2*)&o[(size_t)(tokbase + row0)*DIMV + h*DHEAD + nt*8 + tig*2] =
                        __floats2half2_rn(oa[nt][0], oa[nt][1]);
            }
            if (row0 + 8 < NT) {
                #pragma unroll
                for (int nt = 0; nt < 4; nt++)
                    *(__half2*)&o[(size_t)(tokbase + row0 + 8)*DIMV + h*DHEAD + nt*8 + tig*2] =
                        __floats2half2_rn(oa[nt][2], oa[nt][3]);
            }
        }
        __syncwarp();
    }
}

#define ATTN_SMEM_65 (8 * ((80*80) + (80*80) + 32*(80*2+16)))
#define ATTN_SMEM_64 (8 * ((64*80) + (64*80) + 32*(64*2+16)))

// ================= fp16 GEMM, templated M tile =================
// MI=4 -> BM=128 (R13-proven, 64x32 warp tiles); MI=2 -> BM=64 (region path: more CTAs)
// epi 0: C = AB; 1: C = AB+bias+C; 2: Oh = gelu(AB+bias); 3: Oh = AB;
// epi 5: Cout[permuted unpack location] = AB + bias + C   (final layer, kills unpack)
#define BN 128
#define BK 64
#define NSTG 3
#define ROWB 144
#define STGB(MI) (((MI)*32 + BN) * ROWB)
#define SMEMG(MI) (NSTG * STGB(MI))

template<int MI>
__global__ __launch_bounds__(256, 2) void gemm_mma(
    const __half* __restrict__ A, const __half* __restrict__ B,
    const float* __restrict__ bias, float* __restrict__ C,
    __half* __restrict__ Oh, float* __restrict__ Cout,
    int N, int K, int epi, int cs)
{
    constexpr int BM = MI*32;
    extern __shared__ char smem[];
    const uint32_t sb = smem_to_u32(smem);
    const int tid = threadIdx.x;
    const int bm = blockIdx.y * BM;
    const int bn = blockIdx.x * BN;
    const int total = K / BK;

    const int wid = tid >> 5, lane = tid & 31;
    const int wm = wid & 1, wn = wid >> 1;

    float acc[MI][4][4];
    #pragma unroll
    for (int mi = 0; mi < MI; mi++)
        #pragma unroll
        for (int ni = 0; ni < 4; ni++)
            #pragma unroll
            for (int r = 0; r < 4; r++) acc[mi][ni][r] = 0.f;

    auto load_chunk = [&](int c) {
        int col = c*BK;
        uint32_t stA = sb + (c % NSTG) * STGB(MI);
        uint32_t stB = stA + BM * ROWB;
        #pragma unroll
        for (int i = 0; i < MI; i++) {            // A: BM rows x 8 segs
            int s = tid + i*256;
            int row = s >> 3, seg = s & 7;
            cp16(stA + row*ROWB + seg*16, A + (size_t)(bm + row)*K + col + seg*8);
        }
        #pragma unroll
        for (int i = 0; i < 4; i++) {             // B: 128 rows x 8 segs
            int s = tid + i*256;
            int row = s >> 3, seg = s & 7;
            cp16(stB + row*ROWB + seg*16, B + (size_t)(bn + row)*K + col + seg*8);
        }
        cp_commit();
    };

    load_chunk(0);
    load_chunk(1);

    for (int c = 0; c < total; c++) {
        if (c == total - 1) asm volatile("cp.async.wait_group 0;\n" ::: "memory");
        else                asm volatile("cp.async.wait_group 1;\n" ::: "memory");
        __syncthreads();
        if (c + 2 < total) load_chunk(c + 2);

        uint32_t stA = sb + (c % NSTG) * STGB(MI);
        uint32_t stB = stA + BM * ROWB;
        #pragma unroll
        for (int ks = 0; ks < 4; ks++) {
            uint32_t a[MI][4];
            #pragma unroll
            for (int mi = 0; mi < MI; mi++) {
                uint32_t addr = stA + (wm*(MI*16) + mi*16 + (lane & 15))*ROWB + ((lane >> 4)*16 + ks*32);
                asm volatile("ldmatrix.sync.aligned.m8n8.x4.shared.b16 {%0,%1,%2,%3}, [%4];"
                    : "=r"(a[mi][0]), "=r"(a[mi][1]), "=r"(a[mi][2]), "=r"(a[mi][3]) : "r"(addr));
            }
            uint32_t b[4][2];
            #pragma unroll
            for (int ni = 0; ni < 4; ni++) {
                uint32_t addr = stB + (wn*32 + ni*8 + (lane & 7))*ROWB + (((lane >> 3) & 1)*16 + ks*32);
                asm volatile("ldmatrix.sync.aligned.m8n8.x2.shared.b16 {%0,%1}, [%2];"
                    : "=r"(b[ni][0]), "=r"(b[ni][1]) : "r"(addr));
            }
            #pragma unroll
            for (int mi = 0; mi < MI; mi++)
                #pragma unroll
                for (int ni = 0; ni < 4; ni++) {
                    asm volatile(
                        "mma.sync.aligned.m16n8k16.row.col.f32.f16.f16.f32 "
                        "{%0,%1,%2,%3}, {%4,%5,%6,%7}, {%8,%9}, {%0,%1,%2,%3};"
                        : "+f"(acc[mi][ni][0]), "+f"(acc[mi][ni][1]),
                          "+f"(acc[mi][ni][2]), "+f"(acc[mi][ni][3])
                        : "r"(a[mi][0]), "r"(a[mi][1]), "r"(a[mi][2]), "r"(a[mi][3]),
                          "r"(b[ni][0]), "r"(b[ni][1]));
                }
        }
    }

    // ---- epilogue ----
    const int g = lane >> 2, tig = lane & 3;
    #pragma unroll
    for (int mi = 0; mi < MI; mi++) {
        #pragma unroll
        for (int ni = 0; ni < 4; ni++) {
            int r0 = bm + wm*(MI*16) + mi*16 + g;
            int cc = bn + wn*32 + ni*8 + tig*2;
            #pragma unroll
            for (int half = 0; half < 2; half++) {
                int r = r0 + half*8;
                float v0 = acc[mi][ni][half*2 + 0];
                float v1 = acc[mi][ni][half*2 + 1];
                if (epi == 0) {
                    float2 st; st.x = v0; st.y = v1;
                    *(float2*)&C[(size_t)r*cs + cc] = st;
                } else if (epi == 1) {
                    float2 bi  = *(const float2*)&bias[cc];
                    float2 res = *(const float2*)&C[(size_t)r*cs + cc];
                    float2 st; st.x = v0 + bi.x + res.x; st.y = v1 + bi.y + res.y;
                    *(float2*)&C[(size_t)r*cs + cc] = st;
                } else if (epi == 2) {
                    float2 bi = *(const float2*)&bias[cc];
                    float g0 = gelu_exact(v0 + bi.x);
                    float g1 = gelu_exact(v1 + bi.y);
                    *(__half2*)&Oh[(size_t)r*cs + cc] = __floats2half2_rn(g0, g1);
                } else if (epi == 3) {
                    *(__half2*)&Oh[(size_t)r*cs + cc] = __floats2half2_rn(v0, v1);
                } else {
                    // epi 5: residual add, write to permuted output (unpack fused)
                    float2 bi  = *(const float2*)&bias[cc];
                    float2 res = *(const float2*)&C[(size_t)r*cs + cc];
                    float2 st; st.x = v0 + bi.x + res.x; st.y = v1 + bi.y + res.y;
                    int win = r / NTOK, t = r - win*NTOK;
                    size_t orow;
                    if (t == 0) {
                        orow = (size_t)(LOCAL_ELEMS/DIMV) + win;
                    } else {
                        int a = t - 1, p1 = a >> 3, p2 = a & 7;
                        int b = win >> 6, rh = (win >> 3) & 7, rw = win & 7;
                        orow = (size_t)(((b*64) + (rh*8 + p1))*64 + (rw*8 + p2));
                    }
                    *(float2*)&Cout[orow*DIMV + cc] = st;
                }
            }
        }
    }
}

// ================= Host driver =================
extern "C" void kernel_launch(void* const* d_in, const int* in_sizes, int n_in,
                              void* d_out, int out_size) {
    const float* local_t  = (const float*)d_in[0];
    const float* region_t = (const float*)d_in[1];
    const float* emb      = (const float*)d_in[2];
    const float* attn_g   = (const float*)d_in[3];
    const float* attn_b   = (const float*)d_in[4];
    const float* wqkv     = (const float*)d_in[5];
    const float* wout     = (const float*)d_in[6];
    const float* bout     = (const float*)d_in[7];
    const float* mlp_g    = (const float*)d_in[8];
    const float* mlp_b    = (const float*)d_in[9];
    const float* w1       = (const float*)d_in[10];
    const float* b1       = (const float*)d_in[11];
    const float* w2       = (const float*)d_in[12];
    const float* b2       = (const float*)d_in[13];
    float* out = (float*)d_out;

    cudaFuncSetAttribute(gemm_mma<4>, cudaFuncAttributeMaxDynamicSharedMemorySize, SMEMG(4));
    cudaFuncSetAttribute(gemm_mma<2>, cudaFuncAttributeMaxDynamicSharedMemorySize, SMEMG(2));
    cudaFuncSetAttribute(attn_tc<NTOK>, cudaFuncAttributeMaxDynamicSharedMemorySize, ATTN_SMEM_65);
    cudaFuncSetAttribute(attn_tc<64>,   cudaFuncAttributeMaxDynamicSharedMemorySize, ATTN_SMEM_64);

    float *xw, *biasT;
    __half *h, *o, *m1, *hr, *orr, *qkv, *qkvr, *Wqkv, *Wout, *W1h, *W2h;
    cudaGetSymbolAddress((void**)&xw,   g_xw);
    cudaGetSymbolAddress((void**)&h,    g_h);
    cudaGetSymbolAddress((void**)&qkv,  g_qkv);
    cudaGetSymbolAddress((void**)&o,    g_o);
    cudaGetSymbolAddress((void**)&m1,   g_m1);
    cudaGetSymbolAddress((void**)&biasT,g_bias);
    cudaGetSymbolAddress((void**)&hr,   g_hr);
    cudaGetSymbolAddress((void**)&qkvr, g_qkvr);
    cudaGetSymbolAddress((void**)&orr,  g_or);
    cudaGetSymbolAddress((void**)&Wqkv, g_Wqkv);
    cudaGetSymbolAddress((void**)&Wout, g_Wout);
    cudaGetSymbolAddress((void**)&W1h,  g_W1h);
    cudaGetSymbolAddress((void**)&W2h,  g_W2h);

    pack_kernel<<<(NROWS*128 + 255)/256, 256>>>(local_t, region_t);
    wconv_all<<<T_W2 + BIAS_BLKS, 256>>>(wqkv, wout, w1, w2, emb);

    for (int l = 0; l < DEPTH; l++) {
        __half* WqT = Wqkv + (size_t)l*SEG_QKV;
        __half* WoT = Wout + (size_t)l*SEG_OUT;
        __half* W1T = W1h + (size_t)l*SEG_W1;
        __half* W2T = W2h + (size_t)l*SEG_W2;
        const float* Bout = bout + (size_t)l*DIMV;
        const float* B1   = b1   + (size_t)l*4*DIMV;
        const float* B2   = b2   + (size_t)l*DIMV;
        const float* Ag   = attn_g + (size_t)l*DIMV;
        const float* Ab   = attn_b + (size_t)l*DIMV;
        const float* Mg   = mlp_g  + (size_t)l*DIMV;
        const float* Mb   = mlp_b  + (size_t)l*DIMV;

        // ---- region self-attention (BM=64 GEMMs: 2x CTAs, half the latency chain) ----
        ln_half<<<NWIN/8, 256>>>(xw, NTOK*DIMV, Ag, Ab, hr);
        gemm_mma<2><<<dim3(3*DIMV/BN, NWIN/64), 256, SMEMG(2)>>>(
            hr, WqT, nullptr, nullptr, qkvr, nullptr, 3*DIMV, DIMV, 3, 3*DIMV);
        attn_tc<64><<<NB, 256, ATTN_SMEM_64>>>(qkvr, nullptr, orr);
        gemm_mma<2><<<dim3(DIMV/BN, NWIN/64), 256, SMEMG(2)>>>(
            orr, WoT, Bout, xw, nullptr, nullptr, DIMV, DIMV, 1, NTOK*DIMV);

        // ---- window attention ----
        ln_half<<<NROWS/8, 256>>>(xw, DIMV, Ag, Ab, h);
        gemm_mma<4><<<dim3(3*DIMV/BN, NROWS/128), 256, SMEMG(4)>>>(
            h, WqT, nullptr, nullptr, qkv, nullptr, 3*DIMV, DIMV, 3, 3*DIMV);
        attn_tc<NTOK><<<NWIN, 256, ATTN_SMEM_65>>>(qkv, biasT, o);
        gemm_mma<4><<<dim3(DIMV/BN, NROWS/128), 256, SMEMG(4)>>>(
            o, WoT, Bout, xw, nullptr, nullptr, DIMV, DIMV, 1, DIMV);

        // ---- MLP ----
        ln_half<<<NROWS/8, 256>>>(xw, DIMV, Mg, Mb, h);
        gemm_mma<4><<<dim3(4*DIMV/BN, NROWS/128), 256, SMEMG(4)>>>(
            h, W1T, B1, nullptr, m1, nullptr, 4*DIMV, DIMV, 2, 4*DIMV);
        if (l < DEPTH - 1) {
            gemm_mma<4><<<dim3(DIMV/BN, NROWS/128), 256, SMEMG(4)>>>(
                m1, W2T, B2, xw, nullptr, nullptr, DIMV, 4*DIMV, 1, DIMV);
        } else {
            // final layer: write residual result directly to permuted output (unpack fused)
            gemm_mma<4><<<dim3(DIMV/BN, NROWS/128), 256, SMEMG(4)>>>(
                m1, W2T, B2, xw, nullptr, out, DIMV, 4*DIMV, 5, DIMV);
        }
    }
}

// round 17
// speedup vs baseline: 1.2213x; 1.0460x over previous
#include <cuda_runtime.h>
#include <cuda_fp16.h>
#include <math.h>
#include <stdint.h>

// ---------------- Problem constants ----------------
#define DIMV    512
#define HEADS   16
#define DHEAD   32
#define NWIN    512
#define NTOK    65
#define NROWS   (NWIN*NTOK)  // 33280
#define NB      8
#define DEPTH   4
#define QSCALE  0.17677669529663687f
#define LOCAL_ELEMS (8*64*64*512)

// ---------------- helpers ----------------
__device__ __forceinline__ uint32_t smem_to_u32(const void* p) {
    uint32_t a;
    asm("{ .reg .u64 t; cvta.to.shared.u64 t, %1; cvt.u32.u64 %0, t; }" : "=r"(a) : "l"(p));
    return a;
}
__device__ __forceinline__ void cp16(uint32_t dst, const void* src) {
    asm volatile("cp.async.cg.shared.global [%0], [%1], 16;\n" :: "r"(dst), "l"(src));
}
__device__ __forceinline__ void cp_commit() { asm volatile("cp.async.commit_group;\n" ::: "memory"); }
__device__ __forceinline__ float gelu_exact(float x) {
    return 0.5f * x * (1.0f + erff(x * 0.70710678118654752f));
}
__device__ __forceinline__ uint32_t h2_u32(__half2 v) {
    return *(uint32_t*)&v;
}

// ================= Scratch =================
__device__ __align__(16) float  g_xw  [NROWS*DIMV];
__device__ __align__(16) __half g_h   [NROWS*DIMV];
__device__ __align__(16) __half g_qkv [NROWS*3*DIMV];
__device__ __align__(16) __half g_o   [NROWS*DIMV];
__device__ __align__(16) __half g_m1  [NROWS*4*DIMV];
__device__ __align__(16) float  g_bias[HEADS*NTOK*NTOK];
__device__ __align__(16) __half g_hr  [NWIN*DIMV];
__device__ __align__(16) __half g_qkvr[NWIN*3*DIMV];
__device__ __align__(16) __half g_or  [NWIN*DIMV];
__device__ __align__(16) __half g_Wqkv[DEPTH*3*DIMV*DIMV];
__device__ __align__(16) __half g_Wout[DEPTH*DIMV*DIMV];
__device__ __align__(16) __half g_W1h [DEPTH*4*DIMV*DIMV];
__device__ __align__(16) __half g_W2h [DEPTH*DIMV*4*DIMV];

// ================= pack (float4-vectorized) =================
__global__ void pack_kernel(const float* __restrict__ local_t, const float* __restrict__ region_t) {
    int idx = blockIdx.x * blockDim.x + threadIdx.x;
    if (idx >= NROWS*128) return;
    int d4 = idx & 127, row = idx >> 7;
    int win = row / NTOK, t = row - win*NTOK;
    float4 v;
    if (t == 0) v = ((const float4*)region_t)[win*128 + d4];
    else {
        int a = t - 1, p1 = a >> 3, p2 = a & 7;
        int b = win >> 6, rh = (win >> 3) & 7, rw = win & 7;
        v = ((const float4*)local_t)[(((b*64) + (rh*8 + p1))*64 + (rw*8 + p2))*128 + d4];
    }
    ((float4*)g_xw)[idx] = v;
}

// ---- coalesced weight conversion: 32x32 tiled transpose + bias table ----
#define SEG_QKV (3*DIMV*DIMV)
#define SEG_OUT (DIMV*DIMV)
#define SEG_W1  (DIMV*4*DIMV)
#define SEG_W2  (4*DIMV*DIMV)
#define BIAS_N  (HEADS*NTOK*NTOK)
#define T_QKV 3072
#define T_OUT (T_QKV + 1024)
#define T_W1  (T_OUT + 4096)
#define T_W2  (T_W1 + 4096)   // 12288
#define BIAS_BLKS ((BIAS_N + 255)/256)

__global__ __launch_bounds__(256) void wconv_all(
    const float* __restrict__ wqkv, const float* __restrict__ wout,
    const float* __restrict__ w1, const float* __restrict__ w2,
    const float* __restrict__ emb)
{
    int bid = blockIdx.x;
    if (bid < T_W2) {
        const float* W; __half* O; int K, N, r;
        if (bid < T_QKV) {
            int l = bid / 768; r = bid - l*768;
            W = wqkv + (size_t)l*SEG_QKV; O = g_Wqkv + (size_t)l*SEG_QKV; K = DIMV; N = 3*DIMV;
        } else if (bid < T_OUT) {
            int q = bid - T_QKV; int l = q / 256; r = q - l*256;
            W = wout + (size_t)l*SEG_OUT; O = g_Wout + (size_t)l*SEG_OUT; K = DIMV; N = DIMV;
        } else if (bid < T_W1) {
            int q = bid - T_OUT; int l = q / 1024; r = q - l*1024;
            W = w1 + (size_t)l*SEG_W1; O = g_W1h + (size_t)l*SEG_W1; K = DIMV; N = 4*DIMV;
        } else {
            int q = bid - T_W1; int l = q / 1024; r = q - l*1024;
            W = w2 + (size_t)l*SEG_W2; O = g_W2h + (size_t)l*SEG_W2; K = 4*DIMV; N = DIMV;
        }
        int tilesN = N >> 5;
        int tk = r / tilesN, tn = r - tk*tilesN;
        int k0 = tk*32, n0 = tn*32;
        __shared__ float tile[32][33];
        int tx = threadIdx.x & 31, ty = threadIdx.x >> 5;
        #pragma unroll
        for (int i = 0; i < 4; i++)
            tile[ty + i*8][tx] = W[(size_t)(k0 + ty + i*8)*N + n0 + tx];
        __syncthreads();
        #pragma unroll
        for (int i = 0; i < 4; i++)
            O[(size_t)(n0 + ty + i*8)*K + k0 + tx] = __float2half_rn(tile[tx][ty + i*8]);
    } else {
        int r = (bid - T_W2)*256 + threadIdx.x;
        if (r >= BIAS_N) return;
        int h = r / (NTOK*NTOK);
        int q = r - h*NTOK*NTOK;
        int i = q / NTOK, j = q - i*NTOK;
        float v = 0.f;
        if (i > 0 && j > 0) {
            int a = i - 1, b = j - 1;
            int r0 = (a >> 3) - (b >> 3) + 7;
            int r1 = (a & 7) - (b & 7) + 7;
            v = emb[(r0 + r1*15)*HEADS + h];
        }
        g_bias[r] = v;
    }
}

// ================= LayerNorm -> fp16, warp-per-row =================
__global__ __launch_bounds__(256) void ln_half(const float* __restrict__ x, int instr,
                                               const float* __restrict__ g,
                                               const float* __restrict__ b,
                                               __half* __restrict__ y) {
    int w = threadIdx.x >> 5, lane = threadIdx.x & 31;
    int row = blockIdx.x*8 + w;
    const float4* xv = (const float4*)(x + (size_t)row*instr);
    float4 v[4];
    float s = 0.f, s2 = 0.f;
    #pragma unroll
    for (int i = 0; i < 4; i++) {
        v[i] = xv[lane + 32*i];
        s  += v[i].x + v[i].y + v[i].z + v[i].w;
        s2 += v[i].x*v[i].x + v[i].y*v[i].y + v[i].z*v[i].z + v[i].w*v[i].w;
    }
    #pragma unroll
    for (int off = 16; off; off >>= 1) {
        s  += __shfl_xor_sync(0xffffffffu, s,  off);
        s2 += __shfl_xor_sync(0xffffffffu, s2, off);
    }
    float mean = s * (1.f/512.f);
    float var  = s2 * (1.f/512.f) - mean*mean;
    float rstd = rsqrtf(var + 1e-3f);
    __half2* p = (__half2*)(y + (size_t)row*DIMV);
    #pragma unroll
    for (int i = 0; i < 4; i++) {
        float4 gg = ((const float4*)g)[lane + 32*i];
        float4 bb = ((const float4*)b)[lane + 32*i];
        __half2 o01 = __floats2half2_rn((v[i].x - mean)*rstd*gg.x + bb.x, (v[i].y - mean)*rstd*gg.y + bb.y);
        __half2 o23 = __floats2half2_rn((v[i].z - mean)*rstd*gg.z + bb.z, (v[i].w - mean)*rstd*gg.w + bb.w);
        p[(lane + 32*i)*2]     = o01;
        p[(lane + 32*i)*2 + 1] = o23;
    }
}

// ================= Tensor-core attention: 4 warps/CTA, 1 head/warp, 3 CTAs/SM =================
template<int NT>
__global__ __launch_bounds__(128) void attn_tc(const __half* __restrict__ qkv,
                                               const float* __restrict__ biasTab,
                                               __half* __restrict__ o) {
    constexpr int TOK_PAD = (NT + 15) & ~15;
    constexpr int ST = TOK_PAD / 8;
    constexpr int QB = TOK_PAD / 16;
    constexpr int KS = TOK_PAD / 16;
    constexpr int QROWB = 80, KROWB = 80, VROWB = TOK_PAD*2 + 16;
    constexpr int PW = TOK_PAD*QROWB + TOK_PAD*KROWB + 32*VROWB;
    extern __shared__ __align__(16) char smattn[];
    const int w = threadIdx.x >> 5, lane = threadIdx.x & 31;
    char* spq = smattn + w * PW;
    char* spk = spq + TOK_PAD*QROWB;
    char* spv = spk + TOK_PAD*KROWB;
    const uint32_t uq = smem_to_u32(spq);
    const uint32_t uk = smem_to_u32(spk);
    const uint32_t uv = smem_to_u32(spv);
    const int tokbase = blockIdx.x * NT;
    const int g = lane >> 2, tig = lane & 3;
    const int h = blockIdx.y*4 + w;          // one head per warp

    for (int p = lane; p < NT*16; p += 32) {
        int tok = p >> 4, d2 = p & 15;
        const __half2* src = (const __half2*)(qkv + (size_t)(tokbase + tok)*(3*DIMV) + h*DHEAD + d2*2);
        __half2 qv = src[0];
        float2 qf = __half22float2(qv);
        *(__half2*)(spq + tok*QROWB + d2*4) = __floats2half2_rn(qf.x*QSCALE, qf.y*QSCALE);
        *(__half2*)(spk + tok*KROWB + d2*4) = src[DIMV/2];
        __half2 vv = src[DIMV];
        *(__half*)(spv + (2*d2)*VROWB   + tok*2) = __low2half(vv);
        *(__half*)(spv + (2*d2+1)*VROWB + tok*2) = __high2half(vv);
    }
    if (TOK_PAD > NT) {
        for (int p = lane; p < 32*(TOK_PAD - NT); p += 32) {
            int d = p / (TOK_PAD - NT), c = p - d*(TOK_PAD - NT);
            *(__half*)(spv + d*VROWB + (NT + c)*2) = __ushort_as_half(0);
        }
    }
    __syncwarp();

    for (int qb = 0; qb < QB; qb++) {
        uint32_t afr[2][4];
        #pragma unroll
        for (int kk = 0; kk < 2; kk++) {
            uint32_t addr = uq + (qb*16 + (lane & 15))*QROWB + (lane >> 4)*16 + kk*32;
            asm volatile("ldmatrix.sync.aligned.m8n8.x4.shared.b16 {%0,%1,%2,%3}, [%4];"
                : "=r"(afr[kk][0]), "=r"(afr[kk][1]), "=r"(afr[kk][2]), "=r"(afr[kk][3]) : "r"(addr));
        }
        float s[ST][4];
        #pragma unroll
        for (int t = 0; t < ST; t++) { s[t][0]=0.f; s[t][1]=0.f; s[t][2]=0.f; s[t][3]=0.f; }
        #pragma unroll
        for (int t = 0; t < ST; t++) {
            #pragma unroll
            for (int kk = 0; kk < 2; kk++) {
                uint32_t b[2];
                uint32_t addr = uk + (t*8 + (lane & 7))*KROWB + ((lane >> 3) & 1)*16 + kk*32;
                asm volatile("ldmatrix.sync.aligned.m8n8.x2.shared.b16 {%0,%1}, [%2];"
                    : "=r"(b[0]), "=r"(b[1]) : "r"(addr));
                asm volatile(
                    "mma.sync.aligned.m16n8k16.row.col.f32.f16.f16.f32 "
                    "{%0,%1,%2,%3}, {%4,%5,%6,%7}, {%8,%9}, {%0,%1,%2,%3};"
                    : "+f"(s[t][0]), "+f"(s[t][1]), "+f"(s[t][2]), "+f"(s[t][3])
                    : "r"(afr[kk][0]), "r"(afr[kk][1]), "r"(afr[kk][2]), "r"(afr[kk][3]),
                      "r"(b[0]), "r"(b[1]));
            }
        }
        const int row0 = qb*16 + g;
        #pragma unroll
        for (int t = 0; t < ST; t++) {
            int c0 = t*8 + tig*2;
            if (biasTab) {
                if (row0 < NT) {
                    if (c0 < NT)     s[t][0] += biasTab[(h*NT + row0)*NT + c0];
                    if (c0 + 1 < NT) s[t][1] += biasTab[(h*NT + row0)*NT + c0 + 1];
                }
                if (row0 + 8 < NT) {
                    if (c0 < NT)     s[t][2] += biasTab[(h*NT + row0 + 8)*NT + c0];
                    if (c0 + 1 < NT) s[t][3] += biasTab[(h*NT + row0 + 8)*NT + c0 + 1];
                }
            }
            if (c0 >= NT)     { s[t][0] = -1e30f; s[t][2] = -1e30f; }
            if (c0 + 1 >= NT) { s[t][1] = -1e30f; s[t][3] = -1e30f; }
        }
        float m0 = -1e30f, m1 = -1e30f;
        #pragma unroll
        for (int t = 0; t < ST; t++) {
            m0 = fmaxf(m0, fmaxf(s[t][0], s[t][1]));
            m1 = fmaxf(m1, fmaxf(s[t][2], s[t][3]));
        }
        m0 = fmaxf(m0, __shfl_xor_sync(0xffffffffu, m0, 1));
        m0 = fmaxf(m0, __shfl_xor_sync(0xffffffffu, m0, 2));
        m1 = fmaxf(m1, __shfl_xor_sync(0xffffffffu, m1, 1));
        m1 = fmaxf(m1, __shfl_xor_sync(0xffffffffu, m1, 2));
        float sum0 = 0.f, sum1 = 0.f;
        #pragma unroll
        for (int t = 0; t < ST; t++) {
            s[t][0] = __expf(s[t][0] - m0); s[t][1] = __expf(s[t][1] - m0);
            s[t][2] = __expf(s[t][2] - m1); s[t][3] = __expf(s[t][3] - m1);
            sum0 += s[t][0] + s[t][1];
            sum1 += s[t][2] + s[t][3];
        }
        sum0 += __shfl_xor_sync(0xffffffffu, sum0, 1);
        sum0 += __shfl_xor_sync(0xffffffffu, sum0, 2);
        sum1 += __shfl_xor_sync(0xffffffffu, sum1, 1);
        sum1 += __shfl_xor_sync(0xffffffffu, sum1, 2);
        float inv0 = 1.f / sum0, inv1 = 1.f / sum1;
        uint32_t pa[KS][4];
        #pragma unroll
        for (int ph = 0; ph < KS; ph++) {
            int t0 = 2*ph, t1 = 2*ph + 1;
            pa[ph][0] = h2_u32(__floats2half2_rn(s[t0][0]*inv0, s[t0][1]*inv0));
            pa[ph][1] = h2_u32(__floats2half2_rn(s[t0][2]*inv1, s[t0][3]*inv1));
            pa[ph][2] = h2_u32(__floats2half2_rn(s[t1][0]*inv0, s[t1][1]*inv0));
            pa[ph][3] = h2_u32(__floats2half2_rn(s[t1][2]*inv1, s[t1][3]*inv1));
        }
        float oa[4][4];
        #pragma unroll
        for (int nt = 0; nt < 4; nt++) { oa[nt][0]=0.f; oa[nt][1]=0.f; oa[nt][2]=0.f; oa[nt][3]=0.f; }
        #pragma unroll
        for (int ksi = 0; ksi < KS; ksi++) {
            #pragma unroll
            for (int nt = 0; nt < 4; nt++) {
                uint32_t b[2];
                uint32_t addr = uv + (nt*8 + (lane & 7))*VROWB + (ksi*16 + ((lane >> 3) & 1)*8)*2;
                asm volatile("ldmatrix.sync.aligned.m8n8.x2.shared.b16 {%0,%1}, [%2];"
                    : "=r"(b[0]), "=r"(b[1]) : "r"(addr));
                asm volatile(
                    "mma.sync.aligned.m16n8k16.row.col.f32.f16.f16.f32 "
                    "{%0,%1,%2,%3}, {%4,%5,%6,%7}, {%8,%9}, {%0,%1,%2,%3};"
                    : "+f"(oa[nt][0]), "+f"(oa[nt][1]), "+f"(oa[nt][2]), "+f"(oa[nt][3])
                    : "r"(pa[ksi][0]), "r"(pa[ksi][1]), "r"(pa[ksi][2]), "r"(pa[ksi][3]),
                      "r"(b[0]), "r"(b[1]));
            }
        }
        if (row0 < NT) {
            #pragma unroll
            for (int nt = 0; nt < 4; nt++)
                *(__half2*)&o[(size_t)(tokbase + row0)*DIMV + h*DHEAD + nt*8 + tig*2] =
                    __floats2half2_rn(oa[nt][0], oa[nt][1]);
        }
        if (row0 + 8 < NT) {
            #pragma unroll
            for (int nt = 0; nt < 4; nt++)
                *(__half2*)&o[(size_t)(tokbase + row0 + 8)*DIMV + h*DHEAD + nt*8 + tig*2] =
                    __floats2half2_rn(oa[nt][2], oa[nt][3]);
        }
    }
}

#define ATTN_SMEM_65 (4 * ((80*80) + (80*80) + 32*(80*2+16)))   // 73728  -> 3 CTAs/SM
#define ATTN_SMEM_64 (4 * ((64*80) + (64*80) + 32*(64*2+16)))   // 59392

// ================= fp16 GEMM, templated M tile (R16-proven) =================
#define BN 128
#define BK 64
#define NSTG 3
#define ROWB 144
#define STGB(MI) (((MI)*32 + BN) * ROWB)
#define SMEMG(MI) (NSTG * STGB(MI))

template<int MI>
__global__ __launch_bounds__(256, 2) void gemm_mma(
    const __half* __restrict__ A, const __half* __restrict__ B,
    const float* __restrict__ bias, float* __restrict__ C,
    __half* __restrict__ Oh, float* __restrict__ Cout,
    int N, int K, int epi, int cs)
{
    constexpr int BM = MI*32;
    extern __shared__ char smem[];
    const uint32_t sb = smem_to_u32(smem);
    const int tid = threadIdx.x;
    const int bm = blockIdx.y * BM;
    const int bn = blockIdx.x * BN;
    const int total = K / BK;

    const int wid = tid >> 5, lane = tid & 31;
    const int wm = wid & 1, wn = wid >> 1;

    float acc[MI][4][4];
    #pragma unroll
    for (int mi = 0; mi < MI; mi++)
        #pragma unroll
        for (int ni = 0; ni < 4; ni++)
            #pragma unroll
            for (int r = 0; r < 4; r++) acc[mi][ni][r] = 0.f;

    auto load_chunk = [&](int c) {
        int col = c*BK;
        uint32_t stA = sb + (c % NSTG) * STGB(MI);
        uint32_t stB = stA + BM * ROWB;
        #pragma unroll
        for (int i = 0; i < MI; i++) {
            int s = tid + i*256;
            int row = s >> 3, seg = s & 7;
            cp16(stA + row*ROWB + seg*16, A + (size_t)(bm + row)*K + col + seg*8);
        }
        #pragma unroll
        for (int i = 0; i < 4; i++) {
            int s = tid + i*256;
            int row = s >> 3, seg = s & 7;
            cp16(stB + row*ROWB + seg*16, B + (size_t)(bn + row)*K + col + seg*8);
        }
        cp_commit();
    };

    load_chunk(0);
    load_chunk(1);

    for (int c = 0; c < total; c++) {
        if (c == total - 1) asm volatile("cp.async.wait_group 0;\n" ::: "memory");
        else                asm volatile("cp.async.wait_group 1;\n" ::: "memory");
        __syncthreads();
        if (c + 2 < total) load_chunk(c + 2);

        uint32_t stA = sb + (c % NSTG) * STGB(MI);
        uint32_t stB = stA + BM * ROWB;
        #pragma unroll
        for (int ks = 0; ks < 4; ks++) {
            uint32_t a[MI][4];
            #pragma unroll
            for (int mi = 0; mi < MI; mi++) {
                uint32_t addr = stA + (wm*(MI*16) + mi*16 + (lane & 15))*ROWB + ((lane >> 4)*16 + ks*32);
                asm volatile("ldmatrix.sync.aligned.m8n8.x4.shared.b16 {%0,%1,%2,%3}, [%4];"
                    : "=r"(a[mi][0]), "=r"(a[mi][1]), "=r"(a[mi][2]), "=r"(a[mi][3]) : "r"(addr));
            }
            uint32_t b[4][2];
            #pragma unroll
            for (int ni = 0; ni < 4; ni++) {
                uint32_t addr = stB + (wn*32 + ni*8 + (lane & 7))*ROWB + (((lane >> 3) & 1)*16 + ks*32);
                asm volatile("ldmatrix.sync.aligned.m8n8.x2.shared.b16 {%0,%1}, [%2];"
                    : "=r"(b[ni][0]), "=r"(b[ni][1]) : "r"(addr));
            }
            #pragma unroll
            for (int mi = 0; mi < MI; mi++)
                #pragma unroll
                for (int ni = 0; ni < 4; ni++) {
                    asm volatile(
                        "mma.sync.aligned.m16n8k16.row.col.f32.f16.f16.f32 "
                        "{%0,%1,%2,%3}, {%4,%5,%6,%7}, {%8,%9}, {%0,%1,%2,%3};"
                        : "+f"(acc[mi][ni][0]), "+f"(acc[mi][ni][1]),
                          "+f"(acc[mi][ni][2]), "+f"(acc[mi][ni][3])
                        : "r"(a[mi][0]), "r"(a[mi][1]), "r"(a[mi][2]), "r"(a[mi][3]),
                          "r"(b[ni][0]), "r"(b[ni][1]));
                }
        }
    }

    // ---- epilogue ----
    const int g = lane >> 2, tig = lane & 3;
    #pragma unroll
    for (int mi = 0; mi < MI; mi++) {
        #pragma unroll
        for (int ni = 0; ni < 4; ni++) {
            int r0 = bm + wm*(MI*16) + mi*16 + g;
            int cc = bn + wn*32 + ni*8 + tig*2;
            #pragma unroll
            for (int half = 0; half < 2; half++) {
                int r = r0 + half*8;
                float v0 = acc[mi][ni][half*2 + 0];
                float v1 = acc[mi][ni][half*2 + 1];
                if (epi == 0) {
                    float2 st; st.x = v0; st.y = v1;
                    *(float2*)&C[(size_t)r*cs + cc] = st;
                } else if (epi == 1) {
                    float2 bi  = *(const float2*)&bias[cc];
                    float2 res = *(const float2*)&C[(size_t)r*cs + cc];
                    float2 st; st.x = v0 + bi.x + res.x; st.y = v1 + bi.y + res.y;
                    *(float2*)&C[(size_t)r*cs + cc] = st;
                } else if (epi == 2) {
                    float2 bi = *(const float2*)&bias[cc];
                    float g0 = gelu_exact(v0 + bi.x);
                    float g1 = gelu_exact(v1 + bi.y);
                    *(__half2*)&Oh[(size_t)r*cs + cc] = __floats2half2_rn(g0, g1);
                } else if (epi == 3) {
                    *(__half2*)&Oh[(size_t)r*cs + cc] = __floats2half2_rn(v0, v1);
                } else {
                    float2 bi  = *(const float2*)&bias[cc];
                    float2 res = *(const float2*)&C[(size_t)r*cs + cc];
                    float2 st; st.x = v0 + bi.x + res.x; st.y = v1 + bi.y + res.y;
                    int win = r / NTOK, t = r - win*NTOK;
                    size_t orow;
                    if (t == 0) {
                        orow = (size_t)(LOCAL_ELEMS/DIMV) + win;
                    } else {
                        int a = t - 1, p1 = a >> 3, p2 = a & 7;
                        int b = win >> 6, rh = (win >> 3) & 7, rw = win & 7;
                        orow = (size_t)(((b*64) + (rh*8 + p1))*64 + (rw*8 + p2));
                    }
                    *(float2*)&Cout[orow*DIMV + cc] = st;
                }
            }
        }
    }
}

// ================= Host driver =================
extern "C" void kernel_launch(void* const* d_in, const int* in_sizes, int n_in,
                              void* d_out, int out_size) {
    const float* local_t  = (const float*)d_in[0];
    const float* region_t = (const float*)d_in[1];
    const float* emb      = (const float*)d_in[2];
    const float* attn_g   = (const float*)d_in[3];
    const float* attn_b   = (const float*)d_in[4];
    const float* wqkv     = (const float*)d_in[5];
    const float* wout     = (const float*)d_in[6];
    const float* bout     = (const float*)d_in[7];
    const float* mlp_g    = (const float*)d_in[8];
    const float* mlp_b    = (const float*)d_in[9];
    const float* w1       = (const float*)d_in[10];
    const float* b1       = (const float*)d_in[11];
    const float* w2       = (const float*)d_in[12];
    const float* b2       = (const float*)d_in[13];
    float* out = (float*)d_out;

    cudaFuncSetAttribute(gemm_mma<4>, cudaFuncAttributeMaxDynamicSharedMemorySize, SMEMG(4));
    cudaFuncSetAttribute(gemm_mma<2>, cudaFuncAttributeMaxDynamicSharedMemorySize, SMEMG(2));
    cudaFuncSetAttribute(attn_tc<NTOK>, cudaFuncAttributeMaxDynamicSharedMemorySize, ATTN_SMEM_65);
    cudaFuncSetAttribute(attn_tc<64>,   cudaFuncAttributeMaxDynamicSharedMemorySize, ATTN_SMEM_64);

    float *xw, *biasT;
    __half *h, *o, *m1, *hr, *orr, *qkv, *qkvr, *Wqkv, *Wout, *W1h, *W2h;
    cudaGetSymbolAddress((void**)&xw,   g_xw);
    cudaGetSymbolAddress((void**)&h,    g_h);
    cudaGetSymbolAddress((void**)&qkv,  g_qkv);
    cudaGetSymbolAddress((void**)&o,    g_o);
    cudaGetSymbolAddress((void**)&m1,   g_m1);
    cudaGetSymbolAddress((void**)&biasT,g_bias);
    cudaGetSymbolAddress((void**)&hr,   g_hr);
    cudaGetSymbolAddress((void**)&qkvr, g_qkvr);
    cudaGetSymbolAddress((void**)&orr,  g_or);
    cudaGetSymbolAddress((void**)&Wqkv, g_Wqkv);
    cudaGetSymbolAddress((void**)&Wout, g_Wout);
    cudaGetSymbolAddress((void**)&W1h,  g_W1h);
    cudaGetSymbolAddress((void**)&W2h,  g_W2h);

    pack_kernel<<<(NROWS*128 + 255)/256, 256>>>(local_t, region_t);
    wconv_all<<<T_W2 + BIAS_BLKS, 256>>>(wqkv, wout, w1, w2, emb);

    for (int l = 0; l < DEPTH; l++) {
        __half* WqT = Wqkv + (size_t)l*SEG_QKV;
        __half* WoT = Wout + (size_t)l*SEG_OUT;
        __half* W1T = W1h + (size_t)l*SEG_W1;
        __half* W2T = W2h + (size_t)l*SEG_W2;
        const float* Bout = bout + (size_t)l*DIMV;
        const float* B1   = b1   + (size_t)l*4*DIMV;
        const float* B2   = b2   + (size_t)l*DIMV;
        const float* Ag   = attn_g + (size_t)l*DIMV;
        const float* Ab   = attn_b + (size_t)l*DIMV;
        const float* Mg   = mlp_g  + (size_t)l*DIMV;
        const float* Mb   = mlp_b  + (size_t)l*DIMV;

        // ---- region self-attention ----
        ln_half<<<NWIN/8, 256>>>(xw, NTOK*DIMV, Ag, Ab, hr);
        gemm_mma<2><<<dim3(3*DIMV/BN, NWIN/64), 256, SMEMG(2)>>>(
            hr, WqT, nullptr, nullptr, qkvr, nullptr, 3*DIMV, DIMV, 3, 3*DIMV);
        attn_tc<64><<<dim3(NB, 4), 128, ATTN_SMEM_64>>>(qkvr, nullptr, orr);
        gemm_mma<2><<<dim3(DIMV/BN, NWIN/64), 256, SMEMG(2)>>>(
            orr, WoT, Bout, xw, nullptr, nullptr, DIMV, DIMV, 1, NTOK*DIMV);

        // ---- window attention ----
        ln_half<<<NROWS/8, 256>>>(xw, DIMV, Ag, Ab, h);
        gemm_mma<4><<<dim3(3*DIMV/BN, NROWS/128), 256, SMEMG(4)>>>(
            h, WqT, nullptr, nullptr, qkv, nullptr, 3*DIMV, DIMV, 3, 3*DIMV);
        attn_tc<NTOK><<<dim3(NWIN, 4), 128, ATTN_SMEM_65>>>(qkv, biasT, o);
        gemm_mma<4><<<dim3(DIMV/BN, NROWS/128), 256, SMEMG(4)>>>(
            o, WoT, Bout, xw, nullptr, nullptr, DIMV, DIMV, 1, DIMV);

        // ---- MLP ----
        ln_half<<<NROWS/8, 256>>>(xw, DIMV, Mg, Mb, h);
        gemm_mma<4><<<dim3(4*DIMV/BN, NROWS/128), 256, SMEMG(4)>>>(
            h, W1T, B1, nullptr, m1, nullptr, 4*DIMV, DIMV, 2, 4*DIMV);
        if (l < DEPTH - 1) {
            gemm_mma<4><<<dim3(DIMV/BN, NROWS/128), 256, SMEMG(4)>>>(
                m1, W2T, B2, xw, nullptr, nullptr, DIMV, 4*DIMV, 1, DIMV);
        } else {
            gemm_mma<4><<<dim3(DIMV/BN, NROWS/128), 256, SMEMG(4)>>>(
                m1, W2T, B2, xw, nullptr, out, DIMV, 4*DIMV, 5, DIMV);
        }
    }
}